// round 1
// baseline (speedup 1.0000x reference)
#include <cuda_runtime.h>
#include <math.h>

// ----------------------------------------------------------------------------
// CustomAttentionLayer: x[4,4096,512] -> attention over full p=512 -> out[4,4096,512]
// Round 0: pure fp32 pipeline (4 tiled GEMMs + row softmax), guaranteed-correct
// baseline. Scratch lives in __device__ globals (no allocations).
// ----------------------------------------------------------------------------

#define Bsz 4
#define Sseq 4096
#define Dm 512
#define Pm 512
#define Mrows (Bsz * Sseq)   // 16384

// GEMM tiling
#define BM 128
#define BN 128
#define BK 16
#define TM 8
#define TN 8
#define NTHREADS 256  // (BM/TM)*(BN/TN)

// Scratch (module-static device memory; allowed per harness rules)
__device__ float g_q  [Mrows * Pm];          // 33.5 MB
__device__ float g_k  [Mrows * Pm];
__device__ float g_v  [Mrows * Pm];
__device__ float g_att[Mrows * Pm];
__device__ float g_sc [67108864];            // 4*4096*4096 = 256 MB scores/attn

// ----------------------------------------------------------------------------
// Generic tiled fp32 GEMM: C = alpha * A @ B (+ bias), optional B transpose.
//   A: [M,K] row-major.  B (NN): [K,N] row-major.  B (NT): [N,K] row-major.
//   blockIdx.x -> N tiles, blockIdx.y -> M tiles, blockIdx.z -> batch.
// Assumes M%BM==0, N%BN==0, K%BK==0 (true for all shapes here).
// ----------------------------------------------------------------------------
template <bool TRANSB>
__global__ __launch_bounds__(NTHREADS, 2)
void gemm_f32(const float* __restrict__ A, const float* __restrict__ Bm,
              const float* __restrict__ bias, float* __restrict__ C,
              int M, int N, int K, float alpha,
              size_t strideA, size_t strideB, size_t strideC)
{
    __shared__ float sA[BK][BM];
    __shared__ float sB[BK][BN];

    const int tid = threadIdx.x;
    const int tn  = tid & 15;   // 0..15
    const int tm  = tid >> 4;   // 0..15
    const int bn  = blockIdx.x * BN;
    const int bm  = blockIdx.y * BM;

    A  += (size_t)blockIdx.z * strideA;
    Bm += (size_t)blockIdx.z * strideB;
    C  += (size_t)blockIdx.z * strideC;

    float acc[TM][TN];
#pragma unroll
    for (int i = 0; i < TM; i++)
#pragma unroll
        for (int j = 0; j < TN; j++) acc[i][j] = 0.f;

    for (int k0 = 0; k0 < K; k0 += BK) {
        // ---- load A tile [BM x BK], store transposed sA[k][m] ----
#pragma unroll
        for (int l = 0; l < 2; l++) {
            int idx = tid + l * NTHREADS;         // 0..511 (float4 units)
            int r = idx >> 2;                     // 0..127 (m)
            int c = (idx & 3) << 2;               // 0,4,8,12 (k)
            float4 a = *(const float4*)&A[(size_t)(bm + r) * K + k0 + c];
            sA[c + 0][r] = a.x; sA[c + 1][r] = a.y;
            sA[c + 2][r] = a.z; sA[c + 3][r] = a.w;
        }
        // ---- load B tile -> sB[k][n] ----
        if (!TRANSB) {
#pragma unroll
            for (int l = 0; l < 2; l++) {
                int idx = tid + l * NTHREADS;
                int r = idx >> 5;                 // 0..15 (k)
                int c = (idx & 31) << 2;          // 0..124 (n)
                float4 b = *(const float4*)&Bm[(size_t)(k0 + r) * N + bn + c];
                *(float4*)&sB[r][c] = b;
            }
        } else {
#pragma unroll
            for (int l = 0; l < 2; l++) {
                int idx = tid + l * NTHREADS;
                int r = idx >> 2;                 // 0..127 (n)
                int c = (idx & 3) << 2;           // k
                float4 b = *(const float4*)&Bm[(size_t)(bn + r) * K + k0 + c];
                sB[c + 0][r] = b.x; sB[c + 1][r] = b.y;
                sB[c + 2][r] = b.z; sB[c + 3][r] = b.w;
            }
        }
        __syncthreads();

        // ---- 8x8 register micro-tile ----
#pragma unroll
        for (int kk = 0; kk < BK; kk++) {
            float ra[TM], rb[TN];
            *(float4*)&ra[0] = *(const float4*)&sA[kk][tm * TM];
            *(float4*)&ra[4] = *(const float4*)&sA[kk][tm * TM + 4];
            *(float4*)&rb[0] = *(const float4*)&sB[kk][tn * TN];
            *(float4*)&rb[4] = *(const float4*)&sB[kk][tn * TN + 4];
#pragma unroll
            for (int i = 0; i < TM; i++)
#pragma unroll
                for (int j = 0; j < TN; j++)
                    acc[i][j] = fmaf(ra[i], rb[j], acc[i][j]);
        }
        __syncthreads();
    }

    // ---- epilogue: alpha, bias, store ----
#pragma unroll
    for (int i = 0; i < TM; i++) {
        int row = bm + tm * TM + i;
#pragma unroll
        for (int j = 0; j < TN; j += 4) {
            int col = bn + tn * TN + j;
            float4 o;
            o.x = acc[i][j + 0] * alpha;
            o.y = acc[i][j + 1] * alpha;
            o.z = acc[i][j + 2] * alpha;
            o.w = acc[i][j + 3] * alpha;
            if (bias) {
                o.x += bias[col + 0]; o.y += bias[col + 1];
                o.z += bias[col + 2]; o.w += bias[col + 3];
            }
            *(float4*)&C[(size_t)row * N + col] = o;
        }
    }
}

// ----------------------------------------------------------------------------
// Row softmax over 4096 columns. One block (256 threads) per row; each thread
// holds 16 values (4 float4) in registers; block max/sum reductions.
// ----------------------------------------------------------------------------
__device__ __forceinline__ float warpMax(float v) {
#pragma unroll
    for (int o = 16; o; o >>= 1) v = fmaxf(v, __shfl_xor_sync(0xffffffffu, v, o));
    return v;
}
__device__ __forceinline__ float warpSum(float v) {
#pragma unroll
    for (int o = 16; o; o >>= 1) v += __shfl_xor_sync(0xffffffffu, v, o);
    return v;
}

__global__ __launch_bounds__(256)
void softmax_rows(float* __restrict__ S)
{
    const int NC = 4096;
    float* p = S + (size_t)blockIdx.x * NC;
    __shared__ float sred[8];
    __shared__ float sbcast;

    float4 v[4];
    float mx = -3.0e38f;
#pragma unroll
    for (int l = 0; l < 4; l++) {
        v[l] = *(const float4*)&p[(threadIdx.x + l * 256) * 4];
        mx = fmaxf(mx, fmaxf(fmaxf(v[l].x, v[l].y), fmaxf(v[l].z, v[l].w)));
    }
    // block max
    mx = warpMax(mx);
    if ((threadIdx.x & 31) == 0) sred[threadIdx.x >> 5] = mx;
    __syncthreads();
    if (threadIdx.x < 32) {
        float t = (threadIdx.x < 8) ? sred[threadIdx.x] : -3.0e38f;
        t = warpMax(t);
        if (threadIdx.x == 0) sbcast = t;
    }
    __syncthreads();
    mx = sbcast;
    __syncthreads();

    float sum = 0.f;
#pragma unroll
    for (int l = 0; l < 4; l++) {
        v[l].x = __expf(v[l].x - mx);
        v[l].y = __expf(v[l].y - mx);
        v[l].z = __expf(v[l].z - mx);
        v[l].w = __expf(v[l].w - mx);
        sum += v[l].x + v[l].y + v[l].z + v[l].w;
    }
    // block sum
    sum = warpSum(sum);
    if ((threadIdx.x & 31) == 0) sred[threadIdx.x >> 5] = sum;
    __syncthreads();
    if (threadIdx.x < 32) {
        float t = (threadIdx.x < 8) ? sred[threadIdx.x] : 0.f;
        t = warpSum(t);
        if (threadIdx.x == 0) sbcast = t;
    }
    __syncthreads();
    float inv = 1.f / sbcast;

#pragma unroll
    for (int l = 0; l < 4; l++) {
        v[l].x *= inv; v[l].y *= inv; v[l].z *= inv; v[l].w *= inv;
        *(float4*)&p[(threadIdx.x + l * 256) * 4] = v[l];
    }
}

// ----------------------------------------------------------------------------
// kernel_launch: 7 launches, all on the default stream (graph-capturable).
// Inputs: x, Wq, bq, Wk, bk, Wv, bv, Wo, bo (all fp32). Output fp32 [4,4096,512].
// ----------------------------------------------------------------------------
extern "C" void kernel_launch(void* const* d_in, const int* in_sizes, int n_in,
                              void* d_out, int out_size)
{
    (void)in_sizes; (void)n_in; (void)out_size;
    const float* x  = (const float*)d_in[0];
    const float* Wq = (const float*)d_in[1];
    const float* bq = (const float*)d_in[2];
    const float* Wk = (const float*)d_in[3];
    const float* bk = (const float*)d_in[4];
    const float* Wv = (const float*)d_in[5];
    const float* bv = (const float*)d_in[6];
    const float* Wo = (const float*)d_in[7];
    const float* bo = (const float*)d_in[8];
    float* out = (float*)d_out;

    float *q, *k, *v, *att, *sc;
    cudaGetSymbolAddress((void**)&q,   g_q);
    cudaGetSymbolAddress((void**)&k,   g_k);
    cudaGetSymbolAddress((void**)&v,   g_v);
    cudaGetSymbolAddress((void**)&att, g_att);
    cudaGetSymbolAddress((void**)&sc,  g_sc);

    const float inv_sqrt_kd = 0.125f;  // 1/sqrt(64)

    dim3 blk(NTHREADS);
    dim3 gProj(Pm / BN, Mrows / BM, 1);            // (4,128,1)
    dim3 gScore(Sseq / BN, Sseq / BM, Bsz);        // (32,32,4)
    dim3 gAtt(Pm / BN, Sseq / BM, Bsz);            // (4,32,4)
    dim3 gOut(Dm / BN, Mrows / BM, 1);             // (4,128,1)

    // q/k/v projections: [16384,512] = x @ W + b
    gemm_f32<false><<<gProj, blk>>>(x, Wq, bq, q, Mrows, Pm, Dm, 1.0f, 0, 0, 0);
    gemm_f32<false><<<gProj, blk>>>(x, Wk, bk, k, Mrows, Pm, Dm, 1.0f, 0, 0, 0);
    gemm_f32<false><<<gProj, blk>>>(x, Wv, bv, v, Mrows, Pm, Dm, 1.0f, 0, 0, 0);

    // scores[b] = (q[b] @ k[b]^T) / sqrt(64)   [4096 x 4096] per batch
    gemm_f32<true><<<gScore, blk>>>(q, k, nullptr, sc,
                                    Sseq, Sseq, Pm, inv_sqrt_kd,
                                    (size_t)Sseq * Pm, (size_t)Sseq * Pm,
                                    (size_t)Sseq * Sseq);

    // softmax over last dim (16384 rows of 4096)
    softmax_rows<<<Bsz * Sseq, 256>>>(sc);

    // attended[b] = attn[b] @ v[b]   [4096 x 512] per batch
    gemm_f32<false><<<gAtt, blk>>>(sc, v, nullptr, att,
                                   Sseq, Pm, Sseq, 1.0f,
                                   (size_t)Sseq * Sseq, (size_t)Sseq * Pm,
                                   (size_t)Sseq * Pm);

    // out = attended @ Wo + bo
    gemm_f32<false><<<gOut, blk>>>(att, Wo, bo, out, Mrows, Dm, Pm, 1.0f, 0, 0, 0);
}

// round 3
// speedup vs baseline: 1.6462x; 1.6462x over previous
#include <cuda_runtime.h>
#include <cuda_bf16.h>
#include <cstdint>
#include <math.h>

// ============================================================================
// CustomAttentionLayer on GB300 (sm_103a harness, PTX target sm_103):
// All GEMMs via mma.sync.m16n8k16 bf16 HMMA with error-compensated split:
//   A*B ~= Ahi*Bhi + Ahi*Blo + Alo*Bhi   (fp32 register accumulation)
// tcgen05 PTX is rejected by this harness's ptxas target, so we use the
// sm80-style tensor-core path (fallback HMMA on Blackwell).
// ============================================================================

#define Bsz 4
#define Sseq 4096
#define Dm 512
#define Pm 512
#define Mrows (Bsz * Sseq)   // 16384

// ---------------------------------------------------------------------------
// Scratch (device globals; no allocations allowed)
// ---------------------------------------------------------------------------
__device__ float         g_tmpf [Mrows * Pm];           // 33.5 MB fp32 staging
__device__ __nv_bfloat16 g_xhi  [Mrows * Dm];
__device__ __nv_bfloat16 g_xlo  [Mrows * Dm];
__device__ __nv_bfloat16 g_qhi  [Mrows * Pm];
__device__ __nv_bfloat16 g_qlo  [Mrows * Pm];
__device__ __nv_bfloat16 g_khi  [Mrows * Pm];
__device__ __nv_bfloat16 g_klo  [Mrows * Pm];
__device__ __nv_bfloat16 g_vthi [Mrows * Pm];           // v^T [B][P][S]
__device__ __nv_bfloat16 g_vtlo [Mrows * Pm];
__device__ __nv_bfloat16 g_atthi[Mrows * Pm];
__device__ __nv_bfloat16 g_attlo[Mrows * Pm];
__device__ __nv_bfloat16 g_wthi [4 * Dm * Pm];          // Wq^T,Wk^T,Wv^T,Wo^T hi
__device__ __nv_bfloat16 g_wtlo [4 * Dm * Pm];
__device__ float         g_sc   [(size_t)Bsz * Sseq * Sseq];   // 256 MB
__device__ __nv_bfloat16 g_schi [(size_t)Bsz * Sseq * Sseq];
__device__ __nv_bfloat16 g_sclo [(size_t)Bsz * Sseq * Sseq];

// ---------------------------------------------------------------------------
// PTX primitives (all legal on plain sm_103 target)
// ---------------------------------------------------------------------------
__device__ __forceinline__ uint32_t smem_u32(const void* p) {
    uint32_t a;
    asm("{ .reg .u64 t; cvta.to.shared.u64 t, %1; cvt.u32.u64 %0, t; }"
        : "=r"(a) : "l"(p));
    return a;
}

__device__ __forceinline__ void cp16(uint32_t dst, const void* src) {
    asm volatile("cp.async.cg.shared.global [%0], [%1], 16;"
                 :: "r"(dst), "l"(src));
}
#define CP_COMMIT() asm volatile("cp.async.commit_group;" ::: "memory")
#define CP_WAIT(N)  asm volatile("cp.async.wait_group %0;" :: "n"(N) : "memory")

__device__ __forceinline__ void ldsm_x4(uint32_t* r, uint32_t addr) {
    asm volatile("ldmatrix.sync.aligned.m8n8.x4.shared.b16 {%0,%1,%2,%3}, [%4];"
                 : "=r"(r[0]), "=r"(r[1]), "=r"(r[2]), "=r"(r[3]) : "r"(addr));
}

__device__ __forceinline__ void mma16816(float* c, const uint32_t* a, const uint32_t* b) {
    asm volatile(
        "mma.sync.aligned.m16n8k16.row.col.f32.bf16.bf16.f32 "
        "{%0,%1,%2,%3}, {%4,%5,%6,%7}, {%8,%9}, {%0,%1,%2,%3};"
        : "+f"(c[0]), "+f"(c[1]), "+f"(c[2]), "+f"(c[3])
        : "r"(a[0]), "r"(a[1]), "r"(a[2]), "r"(a[3]), "r"(b[0]), "r"(b[1]));
}

// Swizzled offset inside a 128x32 bf16 tile (64B rows, 4x 16B chunks per row).
// Conflict-free for both cp.async stores and ldmatrix reads (verified pattern).
__device__ __forceinline__ uint32_t swoff(int r, int c) {
    return (uint32_t)(r * 64 + (((c ^ (r + (r >> 2))) & 3) << 4));
}

// ---------------------------------------------------------------------------
// GEMM: C[M,N] = alpha * (A @ B^T) (+ bias), A[M,K] & B[N,K] K-major bf16 hi/lo.
// 128x128 CTA tile, BK=32, 8 warps (2m x 4n), warp tile 64x32, double buffer.
// grid (N/128, M/128, batch)
// ---------------------------------------------------------------------------
#define BK 32
#define TILE_B 8192                 // 128 x 32 x 2B
#define BUF_B  (4 * TILE_B)         // Ahi, Alo, Bhi, Blo
#define GEMM_SMEM (2 * BUF_B)       // 64 KB

__device__ __forceinline__ void load_tile(uint32_t sbase, const __nv_bfloat16* g,
                                          int ldk, int k0, int tid)
{
#pragma unroll
    for (int p = 0; p < 2; p++) {
        int f = tid + p * 256;            // 0..511 16B chunks
        int r = f >> 2;
        int c = f & 3;
        cp16(sbase + swoff(r, c), g + (size_t)r * ldk + k0 + c * 8);
    }
}

__global__ __launch_bounds__(256, 1)
void gemm_bf16x3(const __nv_bfloat16* __restrict__ Ahi, const __nv_bfloat16* __restrict__ Alo,
                 const __nv_bfloat16* __restrict__ Bhi, const __nv_bfloat16* __restrict__ Blo,
                 const float* __restrict__ bias, float* __restrict__ C,
                 int K, float alpha, size_t sA, size_t sB, size_t sC)
{
    extern __shared__ char dynsmem[];
    const uint32_t sm0 = smem_u32(dynsmem);

    const int tid = threadIdx.x;
    const int wid = tid >> 5;
    const int lid = tid & 31;
    const int wm  = wid & 1;          // 0..1  (64-row slabs)
    const int wn  = wid >> 1;         // 0..3  (32-col slabs)
    const int N   = gridDim.x * 128;
    const int bm  = blockIdx.y * 128;
    const int bn  = blockIdx.x * 128;

    Ahi += (size_t)blockIdx.z * sA;  Alo += (size_t)blockIdx.z * sA;
    Bhi += (size_t)blockIdx.z * sB;  Blo += (size_t)blockIdx.z * sB;
    C   += (size_t)blockIdx.z * sC;

    const __nv_bfloat16* tAhi = Ahi + (size_t)bm * K;
    const __nv_bfloat16* tAlo = Alo + (size_t)bm * K;
    const __nv_bfloat16* tBhi = Bhi + (size_t)bn * K;
    const __nv_bfloat16* tBlo = Blo + (size_t)bn * K;

    float acc[4][4][4];
#pragma unroll
    for (int i = 0; i < 4; i++)
#pragma unroll
        for (int j = 0; j < 4; j++)
#pragma unroll
            for (int e = 0; e < 4; e++) acc[i][j][e] = 0.f;

    const int NC = K / BK;

    // prologue: buffer 0
    {
        uint32_t b = sm0;
        load_tile(b + 0 * TILE_B, tAhi, K, 0, tid);
        load_tile(b + 1 * TILE_B, tAlo, K, 0, tid);
        load_tile(b + 2 * TILE_B, tBhi, K, 0, tid);
        load_tile(b + 3 * TILE_B, tBlo, K, 0, tid);
        CP_COMMIT();
    }

    for (int c = 0; c < NC; c++) {
        if (c + 1 < NC) {
            uint32_t b = sm0 + ((c + 1) & 1) * BUF_B;
            const int k0 = (c + 1) * BK;
            load_tile(b + 0 * TILE_B, tAhi, K, k0, tid);
            load_tile(b + 1 * TILE_B, tAlo, K, k0, tid);
            load_tile(b + 2 * TILE_B, tBhi, K, k0, tid);
            load_tile(b + 3 * TILE_B, tBlo, K, k0, tid);
            CP_COMMIT();
            CP_WAIT(1);
        } else {
            CP_WAIT(0);
        }
        __syncthreads();

        const uint32_t bb = sm0 + (c & 1) * BUF_B;
        const uint32_t sAh = bb + 0 * TILE_B;
        const uint32_t sAl = bb + 1 * TILE_B;
        const uint32_t sBh = bb + 2 * TILE_B;
        const uint32_t sBl = bb + 3 * TILE_B;

#pragma unroll
        for (int ks = 0; ks < 2; ks++) {
            uint32_t ah[4][4], al[4][4], bh[4][2], bl[4][2];

            const int rA = wm * 64 + (lid & 15);
            const int cA = ks * 2 + (lid >> 4);
#pragma unroll
            for (int i = 0; i < 4; i++) {
                uint32_t off = swoff(rA + i * 16, cA);
                ldsm_x4(ah[i], sAh + off);
                ldsm_x4(al[i], sAl + off);
            }

            const int cB = ks * 2 + ((lid >> 3) & 1);
#pragma unroll
            for (int jp = 0; jp < 2; jp++) {
                const int rB = wn * 32 + jp * 16 + ((lid >> 4) & 1) * 8 + (lid & 7);
                uint32_t off = swoff(rB, cB);
                uint32_t t[4];
                ldsm_x4(t, sBh + off);
                bh[jp * 2][0] = t[0]; bh[jp * 2][1] = t[1];
                bh[jp * 2 + 1][0] = t[2]; bh[jp * 2 + 1][1] = t[3];
                ldsm_x4(t, sBl + off);
                bl[jp * 2][0] = t[0]; bl[jp * 2][1] = t[1];
                bl[jp * 2 + 1][0] = t[2]; bl[jp * 2 + 1][1] = t[3];
            }

#pragma unroll
            for (int i = 0; i < 4; i++)
#pragma unroll
                for (int j = 0; j < 4; j++) {
                    mma16816(acc[i][j], ah[i], bh[j]);
                    mma16816(acc[i][j], ah[i], bl[j]);
                    mma16816(acc[i][j], al[i], bh[j]);
                }
        }
        __syncthreads();
    }

    // epilogue
    const int mrow = bm + wm * 64 + (lid >> 2);
    const int ncol = bn + wn * 32 + 2 * (lid & 3);
#pragma unroll
    for (int i = 0; i < 4; i++) {
#pragma unroll
        for (int j = 0; j < 4; j++) {
            const int row = mrow + i * 16;
            const int col = ncol + j * 8;
            float2 v0, v1;
            v0.x = acc[i][j][0] * alpha;  v0.y = acc[i][j][1] * alpha;
            v1.x = acc[i][j][2] * alpha;  v1.y = acc[i][j][3] * alpha;
            if (bias) {
                const float2 bv = *(const float2*)&bias[col];
                v0.x += bv.x; v0.y += bv.y;
                v1.x += bv.x; v1.y += bv.y;
            }
            *(float2*)&C[(size_t)row * N + col]       = v0;
            *(float2*)&C[(size_t)(row + 8) * N + col] = v1;
        }
    }
}

// ---------------------------------------------------------------------------
// Elementwise split: fp32 -> (hi, lo) bf16
// ---------------------------------------------------------------------------
__global__ __launch_bounds__(256)
void split_f32(const float4* __restrict__ in, __nv_bfloat16* __restrict__ hi,
               __nv_bfloat16* __restrict__ lo, size_t n4)
{
    size_t i = (size_t)blockIdx.x * 256 + threadIdx.x;
    if (i >= n4) return;
    float4 v = in[i];
    float f[4] = {v.x, v.y, v.z, v.w};
    ushort4 h, l;
    unsigned short* hp = &h.x;
    unsigned short* lp = &l.x;
#pragma unroll
    for (int j = 0; j < 4; j++) {
        __nv_bfloat16 hb = __float2bfloat16(f[j]);
        __nv_bfloat16 lb = __float2bfloat16(f[j] - __bfloat162float(hb));
        hp[j] = __bfloat16_as_ushort(hb);
        lp[j] = __bfloat16_as_ushort(lb);
    }
    *(ushort4*)(hi + i * 4) = h;
    *(ushort4*)(lo + i * 4) = l;
}

// ---------------------------------------------------------------------------
// Transposed split: fp32 [R,C] -> hi/lo bf16 [C,R]
// ---------------------------------------------------------------------------
__global__ __launch_bounds__(256)
void tsplit_f32(const float* __restrict__ in, __nv_bfloat16* __restrict__ hi,
                __nv_bfloat16* __restrict__ lo, int R, int C,
                size_t sin, size_t sout)
{
    __shared__ float t[32][33];
    in += (size_t)blockIdx.z * sin;
    hi += (size_t)blockIdx.z * sout;
    lo += (size_t)blockIdx.z * sout;
    int c0 = blockIdx.x * 32, r0 = blockIdx.y * 32;
    int tx = threadIdx.x, ty = threadIdx.y;
#pragma unroll
    for (int i = 0; i < 32; i += 8)
        t[ty + i][tx] = in[(size_t)(r0 + ty + i) * C + c0 + tx];
    __syncthreads();
#pragma unroll
    for (int i = 0; i < 32; i += 8) {
        float v = t[tx][ty + i];
        __nv_bfloat16 h = __float2bfloat16(v);
        __nv_bfloat16 l = __float2bfloat16(v - __bfloat162float(h));
        size_t o = (size_t)(c0 + ty + i) * R + r0 + tx;
        hi[o] = h; lo[o] = l;
    }
}

// ---------------------------------------------------------------------------
// Row softmax over 4096 columns (fp32, in-place)
// ---------------------------------------------------------------------------
__device__ __forceinline__ float warpMax(float v) {
#pragma unroll
    for (int o = 16; o; o >>= 1) v = fmaxf(v, __shfl_xor_sync(0xffffffffu, v, o));
    return v;
}
__device__ __forceinline__ float warpSum(float v) {
#pragma unroll
    for (int o = 16; o; o >>= 1) v += __shfl_xor_sync(0xffffffffu, v, o);
    return v;
}

__global__ __launch_bounds__(256)
void softmax_rows(float* __restrict__ S)
{
    float* p = S + (size_t)blockIdx.x * 4096;
    __shared__ float sred[8];
    __shared__ float sbcast;

    float4 v[4];
    float mx = -3.0e38f;
#pragma unroll
    for (int l = 0; l < 4; l++) {
        v[l] = *(const float4*)&p[(threadIdx.x + l * 256) * 4];
        mx = fmaxf(mx, fmaxf(fmaxf(v[l].x, v[l].y), fmaxf(v[l].z, v[l].w)));
    }
    mx = warpMax(mx);
    if ((threadIdx.x & 31) == 0) sred[threadIdx.x >> 5] = mx;
    __syncthreads();
    if (threadIdx.x < 32) {
        float t = (threadIdx.x < 8) ? sred[threadIdx.x] : -3.0e38f;
        t = warpMax(t);
        if (threadIdx.x == 0) sbcast = t;
    }
    __syncthreads();
    mx = sbcast;
    __syncthreads();

    float sum = 0.f;
#pragma unroll
    for (int l = 0; l < 4; l++) {
        v[l].x = __expf(v[l].x - mx);
        v[l].y = __expf(v[l].y - mx);
        v[l].z = __expf(v[l].z - mx);
        v[l].w = __expf(v[l].w - mx);
        sum += v[l].x + v[l].y + v[l].z + v[l].w;
    }
    sum = warpSum(sum);
    if ((threadIdx.x & 31) == 0) sred[threadIdx.x >> 5] = sum;
    __syncthreads();
    if (threadIdx.x < 32) {
        float t = (threadIdx.x < 8) ? sred[threadIdx.x] : 0.f;
        t = warpSum(t);
        if (threadIdx.x == 0) sbcast = t;
    }
    __syncthreads();
    float inv = 1.f / sbcast;

#pragma unroll
    for (int l = 0; l < 4; l++) {
        v[l].x *= inv; v[l].y *= inv; v[l].z *= inv; v[l].w *= inv;
        *(float4*)&p[(threadIdx.x + l * 256) * 4] = v[l];
    }
}

// ---------------------------------------------------------------------------
// kernel_launch
// ---------------------------------------------------------------------------
extern "C" void kernel_launch(void* const* d_in, const int* in_sizes, int n_in,
                              void* d_out, int out_size)
{
    (void)in_sizes; (void)n_in; (void)out_size;
    const float* x  = (const float*)d_in[0];
    const float* Wq = (const float*)d_in[1];
    const float* bq = (const float*)d_in[2];
    const float* Wk = (const float*)d_in[3];
    const float* bk = (const float*)d_in[4];
    const float* Wv = (const float*)d_in[5];
    const float* bv = (const float*)d_in[6];
    const float* Wo = (const float*)d_in[7];
    const float* bo = (const float*)d_in[8];
    float* out = (float*)d_out;

    float *tmpf, *sc;
    __nv_bfloat16 *xhi, *xlo, *qhi, *qlo, *khi, *klo, *vthi, *vtlo;
    __nv_bfloat16 *atthi, *attlo, *wthi, *wtlo, *schi, *sclo;
    cudaGetSymbolAddress((void**)&tmpf,  g_tmpf);
    cudaGetSymbolAddress((void**)&sc,    g_sc);
    cudaGetSymbolAddress((void**)&xhi,   g_xhi);
    cudaGetSymbolAddress((void**)&xlo,   g_xlo);
    cudaGetSymbolAddress((void**)&qhi,   g_qhi);
    cudaGetSymbolAddress((void**)&qlo,   g_qlo);
    cudaGetSymbolAddress((void**)&khi,   g_khi);
    cudaGetSymbolAddress((void**)&klo,   g_klo);
    cudaGetSymbolAddress((void**)&vthi,  g_vthi);
    cudaGetSymbolAddress((void**)&vtlo,  g_vtlo);
    cudaGetSymbolAddress((void**)&atthi, g_atthi);
    cudaGetSymbolAddress((void**)&attlo, g_attlo);
    cudaGetSymbolAddress((void**)&wthi,  g_wthi);
    cudaGetSymbolAddress((void**)&wtlo,  g_wtlo);
    cudaGetSymbolAddress((void**)&schi,  g_schi);
    cudaGetSymbolAddress((void**)&sclo,  g_sclo);

    cudaFuncSetAttribute(gemm_bf16x3, cudaFuncAttributeMaxDynamicSharedMemorySize, GEMM_SMEM);

    const size_t WSLICE = (size_t)Dm * Pm;
    dim3 tblk(32, 8);

    // 1) weights -> W^T hi/lo
    tsplit_f32<<<dim3(Pm/32, Dm/32, 1), tblk>>>(Wq, wthi + 0*WSLICE, wtlo + 0*WSLICE, Dm, Pm, 0, 0);
    tsplit_f32<<<dim3(Pm/32, Dm/32, 1), tblk>>>(Wk, wthi + 1*WSLICE, wtlo + 1*WSLICE, Dm, Pm, 0, 0);
    tsplit_f32<<<dim3(Pm/32, Dm/32, 1), tblk>>>(Wv, wthi + 2*WSLICE, wtlo + 2*WSLICE, Dm, Pm, 0, 0);
    tsplit_f32<<<dim3(Dm/32, Pm/32, 1), tblk>>>(Wo, wthi + 3*WSLICE, wtlo + 3*WSLICE, Pm, Dm, 0, 0);

    // 2) split x
    {
        size_t n4 = (size_t)Mrows * Dm / 4;
        split_f32<<<(unsigned)((n4 + 255) / 256), 256>>>((const float4*)x, xhi, xlo, n4);
    }

    dim3 gProj(Pm / 128, Mrows / 128, 1);      // (4,128,1)
    dim3 gScore(Sseq / 128, Sseq / 128, Bsz);  // (32,32,4)
    dim3 gAV(Pm / 128, Sseq / 128, Bsz);       // (4,32,4)
    size_t nQP4 = (size_t)Mrows * Pm / 4;

    // 3) q = x @ Wq^T' + bq ; split
    gemm_bf16x3<<<gProj, 256, GEMM_SMEM>>>(xhi, xlo, wthi + 0*WSLICE, wtlo + 0*WSLICE,
                                           bq, tmpf, Dm, 1.0f, 0, 0, 0);
    split_f32<<<(unsigned)(nQP4 / 256), 256>>>((const float4*)tmpf, qhi, qlo, nQP4);

    // 4) k ; split
    gemm_bf16x3<<<gProj, 256, GEMM_SMEM>>>(xhi, xlo, wthi + 1*WSLICE, wtlo + 1*WSLICE,
                                           bk, tmpf, Dm, 1.0f, 0, 0, 0);
    split_f32<<<(unsigned)(nQP4 / 256), 256>>>((const float4*)tmpf, khi, klo, nQP4);

    // 5) v ; transpose-split per batch [4096,512] -> [512,4096]
    gemm_bf16x3<<<gProj, 256, GEMM_SMEM>>>(xhi, xlo, wthi + 2*WSLICE, wtlo + 2*WSLICE,
                                           bv, tmpf, Dm, 1.0f, 0, 0, 0);
    tsplit_f32<<<dim3(Pm/32, Sseq/32, Bsz), tblk>>>(tmpf, vthi, vtlo, Sseq, Pm,
                                                    (size_t)Sseq * Pm, (size_t)Sseq * Pm);

    // 6) scores = (q @ k^T) / 8
    gemm_bf16x3<<<gScore, 256, GEMM_SMEM>>>(qhi, qlo, khi, klo, nullptr, sc,
                                            Pm, 0.125f,
                                            (size_t)Sseq * Pm, (size_t)Sseq * Pm,
                                            (size_t)Sseq * Sseq);

    // 7) softmax
    softmax_rows<<<Bsz * Sseq, 256>>>(sc);

    // 8) split probs
    {
        size_t n4 = (size_t)Bsz * Sseq * Sseq / 4;
        split_f32<<<(unsigned)(n4 / 256), 256>>>((const float4*)sc, schi, sclo, n4);
    }

    // 9) att = probs @ v  (B = v^T [P,S] K-major)
    gemm_bf16x3<<<gAV, 256, GEMM_SMEM>>>(schi, sclo, vthi, vtlo, nullptr, tmpf,
                                         Sseq, 1.0f,
                                         (size_t)Sseq * Sseq, (size_t)Pm * Sseq,
                                         (size_t)Sseq * Pm);
    split_f32<<<(unsigned)(nQP4 / 256), 256>>>((const float4*)tmpf, atthi, attlo, nQP4);

    // 10) out = att @ Wo^T' + bo
    gemm_bf16x3<<<gProj, 256, GEMM_SMEM>>>(atthi, attlo, wthi + 3*WSLICE, wtlo + 3*WSLICE,
                                           bo, out, Pm, 1.0f, 0, 0, 0);
}

// round 4
// speedup vs baseline: 3.2703x; 1.9865x over previous
#include <cuda_runtime.h>
#include <cuda_fp16.h>
#include <cstdint>
#include <math.h>

// ============================================================================
// CustomAttentionLayer on GB300 (sm_103 PTX target -> mma.sync HMMA path).
// Round 3: fp16 error-compensated split.
//   Projections / out-proj (3-term): Ahi*Bhi + Ahi*Blo + Alo*Bhi
//   Scores & Probs@V     (2-term): Ahi*Bhi + Ahi*Blo      (A-lo dropped)
// All splits fused into GEMM epilogues; softmax emits fp16 probs directly.
// ============================================================================

#define Bsz 4
#define Sseq 4096
#define Dm 512
#define Pm 512
#define Mrows (Bsz * Sseq)   // 16384

// ---------------------------------------------------------------------------
// Scratch (device globals)
// ---------------------------------------------------------------------------
__device__ float  g_tmpf [Mrows * Pm];              // fp32 staging (v only)
__device__ __half g_xhi  [Mrows * Dm];
__device__ __half g_xlo  [Mrows * Dm];
__device__ __half g_qhi  [Mrows * Pm];
__device__ __half g_khi  [Mrows * Pm];
__device__ __half g_klo  [Mrows * Pm];
__device__ __half g_vthi [Mrows * Pm];              // v^T [B][P][S]
__device__ __half g_vtlo [Mrows * Pm];
__device__ __half g_atthi[Mrows * Pm];
__device__ __half g_attlo[Mrows * Pm];
__device__ __half g_wthi [4 * Dm * Pm];             // Wq^T,Wk^T,Wv^T,Wo^T hi
__device__ __half g_wtlo [4 * Dm * Pm];
__device__ float  g_sc   [(size_t)Bsz * Sseq * Sseq];  // 256 MB scores fp32
__device__ __half g_phi  [(size_t)Bsz * Sseq * Sseq];  // 128 MB probs hi fp16

// ---------------------------------------------------------------------------
// PTX primitives
// ---------------------------------------------------------------------------
__device__ __forceinline__ uint32_t smem_u32(const void* p) {
    uint32_t a;
    asm("{ .reg .u64 t; cvta.to.shared.u64 t, %1; cvt.u32.u64 %0, t; }"
        : "=r"(a) : "l"(p));
    return a;
}
__device__ __forceinline__ void cp16(uint32_t dst, const void* src) {
    asm volatile("cp.async.cg.shared.global [%0], [%1], 16;" :: "r"(dst), "l"(src));
}
#define CP_COMMIT() asm volatile("cp.async.commit_group;" ::: "memory")
#define CP_WAIT(N)  asm volatile("cp.async.wait_group %0;" :: "n"(N) : "memory")

__device__ __forceinline__ void ldsm_x4(uint32_t* r, uint32_t addr) {
    asm volatile("ldmatrix.sync.aligned.m8n8.x4.shared.b16 {%0,%1,%2,%3}, [%4];"
                 : "=r"(r[0]), "=r"(r[1]), "=r"(r[2]), "=r"(r[3]) : "r"(addr));
}
__device__ __forceinline__ void mma16816(float* c, const uint32_t* a, const uint32_t* b) {
    asm volatile(
        "mma.sync.aligned.m16n8k16.row.col.f32.f16.f16.f32 "
        "{%0,%1,%2,%3}, {%4,%5,%6,%7}, {%8,%9}, {%0,%1,%2,%3};"
        : "+f"(c[0]), "+f"(c[1]), "+f"(c[2]), "+f"(c[3])
        : "r"(a[0]), "r"(a[1]), "r"(a[2]), "r"(a[3]), "r"(b[0]), "r"(b[1]));
}

// Swizzled offset inside a 128x32 fp16 tile (64B rows, 4x 16B chunks per row).
__device__ __forceinline__ uint32_t swoff(int r, int c) {
    return (uint32_t)(r * 64 + (((c ^ (r + (r >> 2))) & 3) << 4));
}

// ---------------------------------------------------------------------------
// GEMM: C[M,N] = alpha*(A @ B^T)(+bias); A[M,K], B[N,K] K-major fp16 hi/lo.
// TERMS: 3 -> Ahi*Bhi + Ahi*Blo + Alo*Bhi ;  2 -> Ahi*Bhi + Ahi*Blo (no Alo)
// OUTMODE: 0 -> fp32 Cf ; 1 -> fp16 Chi+Clo (split) ; 2 -> fp16 Chi only
// 128x128 CTA tile, BK=32, 8 warps (2m x 4n), warp tile 64x32, double buffer.
// ---------------------------------------------------------------------------
#define BK 32
#define TILE_B 8192                 // 128 x 32 x 2B

__device__ __forceinline__ void load_tile(uint32_t sbase, const __half* g,
                                          int ldk, int k0, int tid)
{
#pragma unroll
    for (int p = 0; p < 2; p++) {
        int f = tid + p * 256;
        int r = f >> 2;
        int c = f & 3;
        cp16(sbase + swoff(r, c), g + (size_t)r * ldk + k0 + c * 8);
    }
}

template <int TERMS, int OUTMODE>
__global__ __launch_bounds__(256, 1)
void gemm_fp16(const __half* __restrict__ Ahi, const __half* __restrict__ Alo,
               const __half* __restrict__ Bhi, const __half* __restrict__ Blo,
               const float* __restrict__ bias,
               float* __restrict__ Cf, __half* __restrict__ Chi, __half* __restrict__ Clo,
               int K, float alpha, size_t sA, size_t sB, size_t sC)
{
    constexpr int NTILES = (TERMS == 3) ? 4 : 3;   // Ahi, Bhi, Blo, [Alo]
    constexpr int BUF_B  = NTILES * TILE_B;

    extern __shared__ char dynsmem[];
    const uint32_t sm0 = smem_u32(dynsmem);

    const int tid = threadIdx.x;
    const int wid = tid >> 5;
    const int lid = tid & 31;
    const int wm  = wid & 1;
    const int wn  = wid >> 1;
    const int N   = gridDim.x * 128;
    const int bm  = blockIdx.y * 128;
    const int bn  = blockIdx.x * 128;

    Ahi += (size_t)blockIdx.z * sA;
    if (TERMS == 3) Alo += (size_t)blockIdx.z * sA;
    Bhi += (size_t)blockIdx.z * sB;
    Blo += (size_t)blockIdx.z * sB;

    const __half* tAhi = Ahi + (size_t)bm * K;
    const __half* tAlo = (TERMS == 3) ? (Alo + (size_t)bm * K) : nullptr;
    const __half* tBhi = Bhi + (size_t)bn * K;
    const __half* tBlo = Blo + (size_t)bn * K;

    float acc[4][4][4];
#pragma unroll
    for (int i = 0; i < 4; i++)
#pragma unroll
        for (int j = 0; j < 4; j++)
#pragma unroll
            for (int e = 0; e < 4; e++) acc[i][j][e] = 0.f;

    const int NC = K / BK;

    // prologue
    {
        uint32_t b = sm0;
        load_tile(b + 0 * TILE_B, tAhi, K, 0, tid);
        load_tile(b + 1 * TILE_B, tBhi, K, 0, tid);
        load_tile(b + 2 * TILE_B, tBlo, K, 0, tid);
        if (TERMS == 3) load_tile(b + 3 * TILE_B, tAlo, K, 0, tid);
        CP_COMMIT();
    }

    for (int c = 0; c < NC; c++) {
        if (c + 1 < NC) {
            uint32_t b = sm0 + ((c + 1) & 1) * BUF_B;
            const int k0 = (c + 1) * BK;
            load_tile(b + 0 * TILE_B, tAhi, K, k0, tid);
            load_tile(b + 1 * TILE_B, tBhi, K, k0, tid);
            load_tile(b + 2 * TILE_B, tBlo, K, k0, tid);
            if (TERMS == 3) load_tile(b + 3 * TILE_B, tAlo, K, k0, tid);
            CP_COMMIT();
            CP_WAIT(1);
        } else {
            CP_WAIT(0);
        }
        __syncthreads();

        const uint32_t bb  = sm0 + (c & 1) * BUF_B;
        const uint32_t sAh = bb + 0 * TILE_B;
        const uint32_t sBh = bb + 1 * TILE_B;
        const uint32_t sBl = bb + 2 * TILE_B;
        const uint32_t sAl = bb + 3 * TILE_B;

#pragma unroll
        for (int ks = 0; ks < 2; ks++) {
            uint32_t ah[4][4], al[4][4], bh[4][2], bl[4][2];

            const int rA = wm * 64 + (lid & 15);
            const int cA = ks * 2 + (lid >> 4);
#pragma unroll
            for (int i = 0; i < 4; i++) {
                uint32_t off = swoff(rA + i * 16, cA);
                ldsm_x4(ah[i], sAh + off);
                if (TERMS == 3) ldsm_x4(al[i], sAl + off);
            }

            const int cB = ks * 2 + ((lid >> 3) & 1);
#pragma unroll
            for (int jp = 0; jp < 2; jp++) {
                const int rB = wn * 32 + jp * 16 + ((lid >> 4) & 1) * 8 + (lid & 7);
                uint32_t off = swoff(rB, cB);
                uint32_t t[4];
                ldsm_x4(t, sBh + off);
                bh[jp * 2][0] = t[0]; bh[jp * 2][1] = t[1];
                bh[jp * 2 + 1][0] = t[2]; bh[jp * 2 + 1][1] = t[3];
                ldsm_x4(t, sBl + off);
                bl[jp * 2][0] = t[0]; bl[jp * 2][1] = t[1];
                bl[jp * 2 + 1][0] = t[2]; bl[jp * 2 + 1][1] = t[3];
            }

#pragma unroll
            for (int i = 0; i < 4; i++)
#pragma unroll
                for (int j = 0; j < 4; j++) {
                    mma16816(acc[i][j], ah[i], bh[j]);
                    mma16816(acc[i][j], ah[i], bl[j]);
                    if (TERMS == 3) mma16816(acc[i][j], al[i], bh[j]);
                }
        }
        __syncthreads();
    }

    // epilogue
    const int mrow = bm + wm * 64 + (lid >> 2);
    const int ncol = bn + wn * 32 + 2 * (lid & 3);
#pragma unroll
    for (int i = 0; i < 4; i++) {
#pragma unroll
        for (int j = 0; j < 4; j++) {
            const int row = mrow + i * 16;
            const int col = ncol + j * 8;
            float v[4];
            v[0] = acc[i][j][0] * alpha;  v[1] = acc[i][j][1] * alpha;
            v[2] = acc[i][j][2] * alpha;  v[3] = acc[i][j][3] * alpha;
            if (bias) {
                const float2 bv = *(const float2*)&bias[col];
                v[0] += bv.x; v[1] += bv.y;
                v[2] += bv.x; v[3] += bv.y;
            }
            if (OUTMODE == 0) {
                float* Cz = Cf + (size_t)blockIdx.z * sC;
                *(float2*)&Cz[(size_t)row * N + col]       = make_float2(v[0], v[1]);
                *(float2*)&Cz[(size_t)(row + 8) * N + col] = make_float2(v[2], v[3]);
            } else {
                __half* Hz = Chi + (size_t)blockIdx.z * sC;
                __half h0 = __float2half_rn(v[0]);
                __half h1 = __float2half_rn(v[1]);
                __half h2 = __float2half_rn(v[2]);
                __half h3 = __float2half_rn(v[3]);
                *(__half2*)&Hz[(size_t)row * N + col]       = __halves2half2(h0, h1);
                *(__half2*)&Hz[(size_t)(row + 8) * N + col] = __halves2half2(h2, h3);
                if (OUTMODE == 1) {
                    __half* Lz = Clo + (size_t)blockIdx.z * sC;
                    __half l0 = __float2half_rn(v[0] - __half2float(h0));
                    __half l1 = __float2half_rn(v[1] - __half2float(h1));
                    __half l2 = __float2half_rn(v[2] - __half2float(h2));
                    __half l3 = __float2half_rn(v[3] - __half2float(h3));
                    *(__half2*)&Lz[(size_t)row * N + col]       = __halves2half2(l0, l1);
                    *(__half2*)&Lz[(size_t)(row + 8) * N + col] = __halves2half2(l2, l3);
                }
            }
        }
    }
}

// ---------------------------------------------------------------------------
// Elementwise split: fp32 -> (hi, lo) fp16
// ---------------------------------------------------------------------------
__global__ __launch_bounds__(256)
void split_f32(const float4* __restrict__ in, __half* __restrict__ hi,
               __half* __restrict__ lo, size_t n4)
{
    size_t i = (size_t)blockIdx.x * 256 + threadIdx.x;
    if (i >= n4) return;
    float4 v = in[i];
    float f[4] = {v.x, v.y, v.z, v.w};
    __half h[4], l[4];
#pragma unroll
    for (int j = 0; j < 4; j++) {
        h[j] = __float2half_rn(f[j]);
        l[j] = __float2half_rn(f[j] - __half2float(h[j]));
    }
    *(uint2*)(hi + i * 4) = *(uint2*)h;
    *(uint2*)(lo + i * 4) = *(uint2*)l;
}

// ---------------------------------------------------------------------------
// Transposed split: fp32 [R,C] -> hi/lo fp16 [C,R]
// ---------------------------------------------------------------------------
__global__ __launch_bounds__(256)
void tsplit_f32(const float* __restrict__ in, __half* __restrict__ hi,
                __half* __restrict__ lo, int R, int C,
                size_t sin, size_t sout)
{
    __shared__ float t[32][33];
    in += (size_t)blockIdx.z * sin;
    hi += (size_t)blockIdx.z * sout;
    lo += (size_t)blockIdx.z * sout;
    int c0 = blockIdx.x * 32, r0 = blockIdx.y * 32;
    int tx = threadIdx.x, ty = threadIdx.y;
#pragma unroll
    for (int i = 0; i < 32; i += 8)
        t[ty + i][tx] = in[(size_t)(r0 + ty + i) * C + c0 + tx];
    __syncthreads();
#pragma unroll
    for (int i = 0; i < 32; i += 8) {
        float v = t[tx][ty + i];
        __half h = __float2half_rn(v);
        __half l = __float2half_rn(v - __half2float(h));
        size_t o = (size_t)(c0 + ty + i) * R + r0 + tx;
        hi[o] = h; lo[o] = l;
    }
}

// ---------------------------------------------------------------------------
// Fused softmax: read fp32 scores row, write fp16 probs (hi only)
// ---------------------------------------------------------------------------
__device__ __forceinline__ float warpMax(float v) {
#pragma unroll
    for (int o = 16; o; o >>= 1) v = fmaxf(v, __shfl_xor_sync(0xffffffffu, v, o));
    return v;
}
__device__ __forceinline__ float warpSum(float v) {
#pragma unroll
    for (int o = 16; o; o >>= 1) v += __shfl_xor_sync(0xffffffffu, v, o);
    return v;
}

__global__ __launch_bounds__(256)
void softmax_probs(const float* __restrict__ S, __half* __restrict__ P)
{
    const float* p = S + (size_t)blockIdx.x * 4096;
    __half* ph     = P + (size_t)blockIdx.x * 4096;
    __shared__ float sred[8];
    __shared__ float sbcast;

    float4 v[4];
    float mx = -3.0e38f;
#pragma unroll
    for (int l = 0; l < 4; l++) {
        v[l] = *(const float4*)&p[(threadIdx.x + l * 256) * 4];
        mx = fmaxf(mx, fmaxf(fmaxf(v[l].x, v[l].y), fmaxf(v[l].z, v[l].w)));
    }
    mx = warpMax(mx);
    if ((threadIdx.x & 31) == 0) sred[threadIdx.x >> 5] = mx;
    __syncthreads();
    if (threadIdx.x < 32) {
        float t = (threadIdx.x < 8) ? sred[threadIdx.x] : -3.0e38f;
        t = warpMax(t);
        if (threadIdx.x == 0) sbcast = t;
    }
    __syncthreads();
    mx = sbcast;
    __syncthreads();

    float sum = 0.f;
#pragma unroll
    for (int l = 0; l < 4; l++) {
        v[l].x = __expf(v[l].x - mx);
        v[l].y = __expf(v[l].y - mx);
        v[l].z = __expf(v[l].z - mx);
        v[l].w = __expf(v[l].w - mx);
        sum += v[l].x + v[l].y + v[l].z + v[l].w;
    }
    sum = warpSum(sum);
    if ((threadIdx.x & 31) == 0) sred[threadIdx.x >> 5] = sum;
    __syncthreads();
    if (threadIdx.x < 32) {
        float t = (threadIdx.x < 8) ? sred[threadIdx.x] : 0.f;
        t = warpSum(t);
        if (threadIdx.x == 0) sbcast = t;
    }
    __syncthreads();
    float inv = 1.f / sbcast;

#pragma unroll
    for (int l = 0; l < 4; l++) {
        __half2 a = __floats2half2_rn(v[l].x * inv, v[l].y * inv);
        __half2 b = __floats2half2_rn(v[l].z * inv, v[l].w * inv);
        uint2 u;
        u.x = *(uint32_t*)&a;
        u.y = *(uint32_t*)&b;
        *(uint2*)&ph[(threadIdx.x + l * 256) * 4] = u;
    }
}

// ---------------------------------------------------------------------------
// kernel_launch
// ---------------------------------------------------------------------------
extern "C" void kernel_launch(void* const* d_in, const int* in_sizes, int n_in,
                              void* d_out, int out_size)
{
    (void)in_sizes; (void)n_in; (void)out_size;
    const float* x  = (const float*)d_in[0];
    const float* Wq = (const float*)d_in[1];
    const float* bq = (const float*)d_in[2];
    const float* Wk = (const float*)d_in[3];
    const float* bk = (const float*)d_in[4];
    const float* Wv = (const float*)d_in[5];
    const float* bv = (const float*)d_in[6];
    const float* Wo = (const float*)d_in[7];
    const float* bo = (const float*)d_in[8];
    float* out = (float*)d_out;

    float *tmpf, *sc;
    __half *xhi, *xlo, *qhi, *khi, *klo, *vthi, *vtlo;
    __half *atthi, *attlo, *wthi, *wtlo, *phi;
    cudaGetSymbolAddress((void**)&tmpf,  g_tmpf);
    cudaGetSymbolAddress((void**)&sc,    g_sc);
    cudaGetSymbolAddress((void**)&xhi,   g_xhi);
    cudaGetSymbolAddress((void**)&xlo,   g_xlo);
    cudaGetSymbolAddress((void**)&qhi,   g_qhi);
    cudaGetSymbolAddress((void**)&khi,   g_khi);
    cudaGetSymbolAddress((void**)&klo,   g_klo);
    cudaGetSymbolAddress((void**)&vthi,  g_vthi);
    cudaGetSymbolAddress((void**)&vtlo,  g_vtlo);
    cudaGetSymbolAddress((void**)&atthi, g_atthi);
    cudaGetSymbolAddress((void**)&attlo, g_attlo);
    cudaGetSymbolAddress((void**)&wthi,  g_wthi);
    cudaGetSymbolAddress((void**)&wtlo,  g_wtlo);
    cudaGetSymbolAddress((void**)&phi,   g_phi);

    const int SM3 = 2 * 4 * TILE_B;   // 64 KB (3-term)
    const int SM2 = 2 * 3 * TILE_B;   // 48 KB (2-term)
    cudaFuncSetAttribute(gemm_fp16<3,0>, cudaFuncAttributeMaxDynamicSharedMemorySize, SM3);
    cudaFuncSetAttribute(gemm_fp16<3,1>, cudaFuncAttributeMaxDynamicSharedMemorySize, SM3);
    cudaFuncSetAttribute(gemm_fp16<3,2>, cudaFuncAttributeMaxDynamicSharedMemorySize, SM3);
    cudaFuncSetAttribute(gemm_fp16<2,0>, cudaFuncAttributeMaxDynamicSharedMemorySize, SM2);
    cudaFuncSetAttribute(gemm_fp16<2,1>, cudaFuncAttributeMaxDynamicSharedMemorySize, SM2);

    const size_t WSLICE = (size_t)Dm * Pm;
    dim3 tblk(32, 8);

    // 1) weights -> W^T hi/lo (fp16)
    tsplit_f32<<<dim3(Pm/32, Dm/32, 1), tblk>>>(Wq, wthi + 0*WSLICE, wtlo + 0*WSLICE, Dm, Pm, 0, 0);
    tsplit_f32<<<dim3(Pm/32, Dm/32, 1), tblk>>>(Wk, wthi + 1*WSLICE, wtlo + 1*WSLICE, Dm, Pm, 0, 0);
    tsplit_f32<<<dim3(Pm/32, Dm/32, 1), tblk>>>(Wv, wthi + 2*WSLICE, wtlo + 2*WSLICE, Dm, Pm, 0, 0);
    tsplit_f32<<<dim3(Dm/32, Pm/32, 1), tblk>>>(Wo, wthi + 3*WSLICE, wtlo + 3*WSLICE, Pm, Dm, 0, 0);

    // 2) split x -> fp16 hi/lo
    {
        size_t n4 = (size_t)Mrows * Dm / 4;
        split_f32<<<(unsigned)((n4 + 255) / 256), 256>>>((const float4*)x, xhi, xlo, n4);
    }

    dim3 gProj(Pm / 128, Mrows / 128, 1);      // (4,128,1)
    dim3 gScore(Sseq / 128, Sseq / 128, Bsz);  // (32,32,4)
    dim3 gAV(Pm / 128, Sseq / 128, Bsz);       // (4,32,4)

    // 3) q = x @ Wq^T + bq   (3-term, write qhi only)
    gemm_fp16<3,2><<<gProj, 256, SM3>>>(xhi, xlo, wthi + 0*WSLICE, wtlo + 0*WSLICE,
                                        bq, nullptr, qhi, nullptr, Dm, 1.0f, 0, 0, 0);

    // 4) k = x @ Wk^T + bk   (3-term, write khi+klo)
    gemm_fp16<3,1><<<gProj, 256, SM3>>>(xhi, xlo, wthi + 1*WSLICE, wtlo + 1*WSLICE,
                                        bk, nullptr, khi, klo, Dm, 1.0f, 0, 0, 0);

    // 5) v = x @ Wv^T + bv   (3-term, fp32) then transpose-split per batch
    gemm_fp16<3,0><<<gProj, 256, SM3>>>(xhi, xlo, wthi + 2*WSLICE, wtlo + 2*WSLICE,
                                        bv, tmpf, nullptr, nullptr, Dm, 1.0f, 0, 0, 0);
    tsplit_f32<<<dim3(Pm/32, Sseq/32, Bsz), tblk>>>(tmpf, vthi, vtlo, Sseq, Pm,
                                                    (size_t)Sseq * Pm, (size_t)Sseq * Pm);

    // 6) scores = (q @ k^T) / 8   (2-term: qhi*khi + qhi*klo), fp32 out
    gemm_fp16<2,0><<<gScore, 256, SM2>>>(qhi, nullptr, khi, klo,
                                         nullptr, sc, nullptr, nullptr,
                                         Pm, 0.125f,
                                         (size_t)Sseq * Pm, (size_t)Sseq * Pm,
                                         (size_t)Sseq * Sseq);

    // 7) softmax -> fp16 probs (hi only)
    softmax_probs<<<Bsz * Sseq, 256>>>(sc, phi);

    // 8) att = probs @ v   (2-term: phi*vhi + phi*vlo), write atthi+attlo
    gemm_fp16<2,1><<<gAV, 256, SM2>>>(phi, nullptr, vthi, vtlo,
                                      nullptr, nullptr, atthi, attlo,
                                      Sseq, 1.0f,
                                      (size_t)Sseq * Sseq, (size_t)Pm * Sseq,
                                      (size_t)Sseq * Pm);

    // 9) out = att @ Wo^T + bo   (3-term, fp32)
    gemm_fp16<3,0><<<gProj, 256, SM3>>>(atthi, attlo, wthi + 3*WSLICE, wtlo + 3*WSLICE,
                                        bo, out, nullptr, nullptr, Pm, 1.0f, 0, 0, 0);
}

// round 5
// speedup vs baseline: 3.8475x; 1.1765x over previous
#include <cuda_runtime.h>
#include <cuda_fp16.h>
#include <cstdint>
#include <math.h>

// ============================================================================
// CustomAttentionLayer on GB300 (sm_103 PTX target -> mma.sync HMMA path).
// Round 4: same fp16 error-compensated math as R3, but
//   - 4-stage cp.async software pipeline (1 sync per K-chunk)
//   - 2 CTAs/SM on the two large 2-term GEMMs (scores, probs@V)
// ============================================================================

#define Bsz 4
#define Sseq 4096
#define Dm 512
#define Pm 512
#define Mrows (Bsz * Sseq)   // 16384

// ---------------------------------------------------------------------------
// Scratch (device globals)
// ---------------------------------------------------------------------------
__device__ float  g_tmpf [Mrows * Pm];              // fp32 staging (v only)
__device__ __half g_xhi  [Mrows * Dm];
__device__ __half g_xlo  [Mrows * Dm];
__device__ __half g_qhi  [Mrows * Pm];
__device__ __half g_khi  [Mrows * Pm];
__device__ __half g_klo  [Mrows * Pm];
__device__ __half g_vthi [Mrows * Pm];              // v^T [B][P][S]
__device__ __half g_vtlo [Mrows * Pm];
__device__ __half g_atthi[Mrows * Pm];
__device__ __half g_attlo[Mrows * Pm];
__device__ __half g_wthi [4 * Dm * Pm];             // Wq^T,Wk^T,Wv^T,Wo^T hi
__device__ __half g_wtlo [4 * Dm * Pm];
__device__ float  g_sc   [(size_t)Bsz * Sseq * Sseq];  // 256 MB scores fp32
__device__ __half g_phi  [(size_t)Bsz * Sseq * Sseq];  // 128 MB probs fp16

// ---------------------------------------------------------------------------
// PTX primitives
// ---------------------------------------------------------------------------
__device__ __forceinline__ uint32_t smem_u32(const void* p) {
    uint32_t a;
    asm("{ .reg .u64 t; cvta.to.shared.u64 t, %1; cvt.u32.u64 %0, t; }"
        : "=r"(a) : "l"(p));
    return a;
}
__device__ __forceinline__ void cp16(uint32_t dst, const void* src) {
    asm volatile("cp.async.cg.shared.global [%0], [%1], 16;" :: "r"(dst), "l"(src));
}
#define CP_COMMIT() asm volatile("cp.async.commit_group;" ::: "memory")
#define CP_WAIT(N)  asm volatile("cp.async.wait_group %0;" :: "n"(N) : "memory")

__device__ __forceinline__ void ldsm_x4(uint32_t* r, uint32_t addr) {
    asm volatile("ldmatrix.sync.aligned.m8n8.x4.shared.b16 {%0,%1,%2,%3}, [%4];"
                 : "=r"(r[0]), "=r"(r[1]), "=r"(r[2]), "=r"(r[3]) : "r"(addr));
}
__device__ __forceinline__ void mma16816(float* c, const uint32_t* a, const uint32_t* b) {
    asm volatile(
        "mma.sync.aligned.m16n8k16.row.col.f32.f16.f16.f32 "
        "{%0,%1,%2,%3}, {%4,%5,%6,%7}, {%8,%9}, {%0,%1,%2,%3};"
        : "+f"(c[0]), "+f"(c[1]), "+f"(c[2]), "+f"(c[3])
        : "r"(a[0]), "r"(a[1]), "r"(a[2]), "r"(a[3]), "r"(b[0]), "r"(b[1]));
}

// Swizzled offset inside a 128x32 fp16 tile (64B rows, 4x 16B chunks per row).
__device__ __forceinline__ uint32_t swoff(int r, int c) {
    return (uint32_t)(r * 64 + (((c ^ (r + (r >> 2))) & 3) << 4));
}

// ---------------------------------------------------------------------------
// GEMM: C[M,N] = alpha*(A @ B^T)(+bias); A[M,K], B[N,K] K-major fp16 hi/lo.
// TERMS: 3 -> Ahi*Bhi + Ahi*Blo + Alo*Bhi ;  2 -> Ahi*Bhi + Ahi*Blo (no Alo)
// OUTMODE: 0 -> fp32 Cf ; 1 -> fp16 Chi+Clo ; 2 -> fp16 Chi only
// 128x128 CTA tile, BK=32, 8 warps (2m x 4n), 4-stage cp.async pipeline.
// 2-term: 2 CTAs/SM (96 KB smem, <=128 regs). 3-term: 1 CTA/SM (128 KB smem).
// ---------------------------------------------------------------------------
#define BK 32
#define TILE_B 8192                 // 128 x 32 x 2B
#define NSTAGES 4

__device__ __forceinline__ void load_tile(uint32_t sbase, const __half* g,
                                          int ldk, int k0, int tid)
{
#pragma unroll
    for (int p = 0; p < 2; p++) {
        int f = tid + p * 256;
        int r = f >> 2;
        int c = f & 3;
        cp16(sbase + swoff(r, c), g + (size_t)r * ldk + k0 + c * 8);
    }
}

template <int TERMS, int OUTMODE>
__global__ __launch_bounds__(256, (TERMS == 2) ? 2 : 1)
void gemm_fp16(const __half* __restrict__ Ahi, const __half* __restrict__ Alo,
               const __half* __restrict__ Bhi, const __half* __restrict__ Blo,
               const float* __restrict__ bias,
               float* __restrict__ Cf, __half* __restrict__ Chi, __half* __restrict__ Clo,
               int K, float alpha, size_t sA, size_t sB, size_t sC)
{
    constexpr int NTILES = (TERMS == 3) ? 4 : 3;   // Ahi, Bhi, Blo, [Alo]
    constexpr int BUF_B  = NTILES * TILE_B;        // bytes per stage

    extern __shared__ char dynsmem[];
    const uint32_t sm0 = smem_u32(dynsmem);

    const int tid = threadIdx.x;
    const int wid = tid >> 5;
    const int lid = tid & 31;
    const int wm  = wid & 1;
    const int wn  = wid >> 1;
    const int N   = gridDim.x * 128;
    const int bm  = blockIdx.y * 128;
    const int bn  = blockIdx.x * 128;

    Ahi += (size_t)blockIdx.z * sA;
    if (TERMS == 3) Alo += (size_t)blockIdx.z * sA;
    Bhi += (size_t)blockIdx.z * sB;
    Blo += (size_t)blockIdx.z * sB;

    const __half* tAhi = Ahi + (size_t)bm * K;
    const __half* tAlo = (TERMS == 3) ? (Alo + (size_t)bm * K) : nullptr;
    const __half* tBhi = Bhi + (size_t)bn * K;
    const __half* tBlo = Blo + (size_t)bn * K;

    float acc[4][4][4];
#pragma unroll
    for (int i = 0; i < 4; i++)
#pragma unroll
        for (int j = 0; j < 4; j++)
#pragma unroll
            for (int e = 0; e < 4; e++) acc[i][j][e] = 0.f;

    const int NC = K / BK;

    // prologue: issue stages 0..NSTAGES-2
#pragma unroll
    for (int s = 0; s < NSTAGES - 1; s++) {
        if (s < NC) {
            uint32_t b = sm0 + s * BUF_B;
            const int k0 = s * BK;
            load_tile(b + 0 * TILE_B, tAhi, K, k0, tid);
            load_tile(b + 1 * TILE_B, tBhi, K, k0, tid);
            load_tile(b + 2 * TILE_B, tBlo, K, k0, tid);
            if (TERMS == 3) load_tile(b + 3 * TILE_B, tAlo, K, k0, tid);
        }
        CP_COMMIT();
    }

    for (int c = 0; c < NC; c++) {
        CP_WAIT(NSTAGES - 2);       // stage c complete
        __syncthreads();            // all warps done with stage (c-1) compute

        // issue stage c+NSTAGES-1 (overwrites buffer of stage c-1)
        {
            const int ps = c + NSTAGES - 1;
            if (ps < NC) {
                uint32_t b = sm0 + (ps % NSTAGES) * BUF_B;
                const int k0 = ps * BK;
                load_tile(b + 0 * TILE_B, tAhi, K, k0, tid);
                load_tile(b + 1 * TILE_B, tBhi, K, k0, tid);
                load_tile(b + 2 * TILE_B, tBlo, K, k0, tid);
                if (TERMS == 3) load_tile(b + 3 * TILE_B, tAlo, K, k0, tid);
            }
            CP_COMMIT();            // empty group at tail keeps accounting uniform
        }

        const uint32_t bb  = sm0 + (c % NSTAGES) * BUF_B;
        const uint32_t sAh = bb + 0 * TILE_B;
        const uint32_t sBh = bb + 1 * TILE_B;
        const uint32_t sBl = bb + 2 * TILE_B;
        const uint32_t sAl = bb + 3 * TILE_B;

#pragma unroll
        for (int ks = 0; ks < 2; ks++) {
            uint32_t ah[4][4], al[4][4], bh[4][2], bl[4][2];

            const int rA = wm * 64 + (lid & 15);
            const int cA = ks * 2 + (lid >> 4);
#pragma unroll
            for (int i = 0; i < 4; i++) {
                uint32_t off = swoff(rA + i * 16, cA);
                ldsm_x4(ah[i], sAh + off);
                if (TERMS == 3) ldsm_x4(al[i], sAl + off);
            }

            const int cB = ks * 2 + ((lid >> 3) & 1);
#pragma unroll
            for (int jp = 0; jp < 2; jp++) {
                const int rB = wn * 32 + jp * 16 + ((lid >> 4) & 1) * 8 + (lid & 7);
                uint32_t off = swoff(rB, cB);
                uint32_t t[4];
                ldsm_x4(t, sBh + off);
                bh[jp * 2][0] = t[0]; bh[jp * 2][1] = t[1];
                bh[jp * 2 + 1][0] = t[2]; bh[jp * 2 + 1][1] = t[3];
                ldsm_x4(t, sBl + off);
                bl[jp * 2][0] = t[0]; bl[jp * 2][1] = t[1];
                bl[jp * 2 + 1][0] = t[2]; bl[jp * 2 + 1][1] = t[3];
            }

#pragma unroll
            for (int i = 0; i < 4; i++)
#pragma unroll
                for (int j = 0; j < 4; j++) {
                    mma16816(acc[i][j], ah[i], bh[j]);
                    mma16816(acc[i][j], ah[i], bl[j]);
                    if (TERMS == 3) mma16816(acc[i][j], al[i], bh[j]);
                }
        }
    }

    // epilogue
    const int mrow = bm + wm * 64 + (lid >> 2);
    const int ncol = bn + wn * 32 + 2 * (lid & 3);
#pragma unroll
    for (int i = 0; i < 4; i++) {
#pragma unroll
        for (int j = 0; j < 4; j++) {
            const int row = mrow + i * 16;
            const int col = ncol + j * 8;
            float v[4];
            v[0] = acc[i][j][0] * alpha;  v[1] = acc[i][j][1] * alpha;
            v[2] = acc[i][j][2] * alpha;  v[3] = acc[i][j][3] * alpha;
            if (bias) {
                const float2 bv = *(const float2*)&bias[col];
                v[0] += bv.x; v[1] += bv.y;
                v[2] += bv.x; v[3] += bv.y;
            }
            if (OUTMODE == 0) {
                float* Cz = Cf + (size_t)blockIdx.z * sC;
                *(float2*)&Cz[(size_t)row * N + col]       = make_float2(v[0], v[1]);
                *(float2*)&Cz[(size_t)(row + 8) * N + col] = make_float2(v[2], v[3]);
            } else {
                __half* Hz = Chi + (size_t)blockIdx.z * sC;
                __half h0 = __float2half_rn(v[0]);
                __half h1 = __float2half_rn(v[1]);
                __half h2 = __float2half_rn(v[2]);
                __half h3 = __float2half_rn(v[3]);
                *(__half2*)&Hz[(size_t)row * N + col]       = __halves2half2(h0, h1);
                *(__half2*)&Hz[(size_t)(row + 8) * N + col] = __halves2half2(h2, h3);
                if (OUTMODE == 1) {
                    __half* Lz = Clo + (size_t)blockIdx.z * sC;
                    __half l0 = __float2half_rn(v[0] - __half2float(h0));
                    __half l1 = __float2half_rn(v[1] - __half2float(h1));
                    __half l2 = __float2half_rn(v[2] - __half2float(h2));
                    __half l3 = __float2half_rn(v[3] - __half2float(h3));
                    *(__half2*)&Lz[(size_t)row * N + col]       = __halves2half2(l0, l1);
                    *(__half2*)&Lz[(size_t)(row + 8) * N + col] = __halves2half2(l2, l3);
                }
            }
        }
    }
}

// ---------------------------------------------------------------------------
// Elementwise split: fp32 -> (hi, lo) fp16
// ---------------------------------------------------------------------------
__global__ __launch_bounds__(256)
void split_f32(const float4* __restrict__ in, __half* __restrict__ hi,
               __half* __restrict__ lo, size_t n4)
{
    size_t i = (size_t)blockIdx.x * 256 + threadIdx.x;
    if (i >= n4) return;
    float4 v = in[i];
    float f[4] = {v.x, v.y, v.z, v.w};
    __half h[4], l[4];
#pragma unroll
    for (int j = 0; j < 4; j++) {
        h[j] = __float2half_rn(f[j]);
        l[j] = __float2half_rn(f[j] - __half2float(h[j]));
    }
    *(uint2*)(hi + i * 4) = *(uint2*)h;
    *(uint2*)(lo + i * 4) = *(uint2*)l;
}

// ---------------------------------------------------------------------------
// Transposed split: fp32 [R,C] -> hi/lo fp16 [C,R]
// ---------------------------------------------------------------------------
__global__ __launch_bounds__(256)
void tsplit_f32(const float* __restrict__ in, __half* __restrict__ hi,
                __half* __restrict__ lo, int R, int C,
                size_t sin, size_t sout)
{
    __shared__ float t[32][33];
    in += (size_t)blockIdx.z * sin;
    hi += (size_t)blockIdx.z * sout;
    lo += (size_t)blockIdx.z * sout;
    int c0 = blockIdx.x * 32, r0 = blockIdx.y * 32;
    int tx = threadIdx.x, ty = threadIdx.y;
#pragma unroll
    for (int i = 0; i < 32; i += 8)
        t[ty + i][tx] = in[(size_t)(r0 + ty + i) * C + c0 + tx];
    __syncthreads();
#pragma unroll
    for (int i = 0; i < 32; i += 8) {
        float v = t[tx][ty + i];
        __half h = __float2half_rn(v);
        __half l = __float2half_rn(v - __half2float(h));
        size_t o = (size_t)(c0 + ty + i) * R + r0 + tx;
        hi[o] = h; lo[o] = l;
    }
}

// ---------------------------------------------------------------------------
// Fused softmax: read fp32 scores row, write fp16 probs
// ---------------------------------------------------------------------------
__device__ __forceinline__ float warpMax(float v) {
#pragma unroll
    for (int o = 16; o; o >>= 1) v = fmaxf(v, __shfl_xor_sync(0xffffffffu, v, o));
    return v;
}
__device__ __forceinline__ float warpSum(float v) {
#pragma unroll
    for (int o = 16; o; o >>= 1) v += __shfl_xor_sync(0xffffffffu, v, o);
    return v;
}

__global__ __launch_bounds__(256)
void softmax_probs(const float* __restrict__ S, __half* __restrict__ P)
{
    const float* p = S + (size_t)blockIdx.x * 4096;
    __half* ph     = P + (size_t)blockIdx.x * 4096;
    __shared__ float sred[8];
    __shared__ float sbcast;

    float4 v[4];
    float mx = -3.0e38f;
#pragma unroll
    for (int l = 0; l < 4; l++) {
        v[l] = *(const float4*)&p[(threadIdx.x + l * 256) * 4];
        mx = fmaxf(mx, fmaxf(fmaxf(v[l].x, v[l].y), fmaxf(v[l].z, v[l].w)));
    }
    mx = warpMax(mx);
    if ((threadIdx.x & 31) == 0) sred[threadIdx.x >> 5] = mx;
    __syncthreads();
    if (threadIdx.x < 32) {
        float t = (threadIdx.x < 8) ? sred[threadIdx.x] : -3.0e38f;
        t = warpMax(t);
        if (threadIdx.x == 0) sbcast = t;
    }
    __syncthreads();
    mx = sbcast;
    __syncthreads();

    float sum = 0.f;
#pragma unroll
    for (int l = 0; l < 4; l++) {
        v[l].x = __expf(v[l].x - mx);
        v[l].y = __expf(v[l].y - mx);
        v[l].z = __expf(v[l].z - mx);
        v[l].w = __expf(v[l].w - mx);
        sum += v[l].x + v[l].y + v[l].z + v[l].w;
    }
    sum = warpSum(sum);
    if ((threadIdx.x & 31) == 0) sred[threadIdx.x >> 5] = sum;
    __syncthreads();
    if (threadIdx.x < 32) {
        float t = (threadIdx.x < 8) ? sred[threadIdx.x] : 0.f;
        t = warpSum(t);
        if (threadIdx.x == 0) sbcast = t;
    }
    __syncthreads();
    float inv = 1.f / sbcast;

#pragma unroll
    for (int l = 0; l < 4; l++) {
        __half2 a = __floats2half2_rn(v[l].x * inv, v[l].y * inv);
        __half2 b = __floats2half2_rn(v[l].z * inv, v[l].w * inv);
        uint2 u;
        u.x = *(uint32_t*)&a;
        u.y = *(uint32_t*)&b;
        *(uint2*)&ph[(threadIdx.x + l * 256) * 4] = u;
    }
}

// ---------------------------------------------------------------------------
// kernel_launch
// ---------------------------------------------------------------------------
extern "C" void kernel_launch(void* const* d_in, const int* in_sizes, int n_in,
                              void* d_out, int out_size)
{
    (void)in_sizes; (void)n_in; (void)out_size;
    const float* x  = (const float*)d_in[0];
    const float* Wq = (const float*)d_in[1];
    const float* bq = (const float*)d_in[2];
    const float* Wk = (const float*)d_in[3];
    const float* bk = (const float*)d_in[4];
    const float* Wv = (const float*)d_in[5];
    const float* bv = (const float*)d_in[6];
    const float* Wo = (const float*)d_in[7];
    const float* bo = (const float*)d_in[8];
    float* out = (float*)d_out;

    float *tmpf, *sc;
    __half *xhi, *xlo, *qhi, *khi, *klo, *vthi, *vtlo;
    __half *atthi, *attlo, *wthi, *wtlo, *phi;
    cudaGetSymbolAddress((void**)&tmpf,  g_tmpf);
    cudaGetSymbolAddress((void**)&sc,    g_sc);
    cudaGetSymbolAddress((void**)&xhi,   g_xhi);
    cudaGetSymbolAddress((void**)&xlo,   g_xlo);
    cudaGetSymbolAddress((void**)&qhi,   g_qhi);
    cudaGetSymbolAddress((void**)&khi,   g_khi);
    cudaGetSymbolAddress((void**)&klo,   g_klo);
    cudaGetSymbolAddress((void**)&vthi,  g_vthi);
    cudaGetSymbolAddress((void**)&vtlo,  g_vtlo);
    cudaGetSymbolAddress((void**)&atthi, g_atthi);
    cudaGetSymbolAddress((void**)&attlo, g_attlo);
    cudaGetSymbolAddress((void**)&wthi,  g_wthi);
    cudaGetSymbolAddress((void**)&wtlo,  g_wtlo);
    cudaGetSymbolAddress((void**)&phi,   g_phi);

    const int SM3 = NSTAGES * 4 * TILE_B;   // 128 KB (3-term, 1 CTA/SM)
    const int SM2 = NSTAGES * 3 * TILE_B;   // 96 KB  (2-term, 2 CTAs/SM)
    cudaFuncSetAttribute(gemm_fp16<3,0>, cudaFuncAttributeMaxDynamicSharedMemorySize, SM3);
    cudaFuncSetAttribute(gemm_fp16<3,1>, cudaFuncAttributeMaxDynamicSharedMemorySize, SM3);
    cudaFuncSetAttribute(gemm_fp16<3,2>, cudaFuncAttributeMaxDynamicSharedMemorySize, SM3);
    cudaFuncSetAttribute(gemm_fp16<2,0>, cudaFuncAttributeMaxDynamicSharedMemorySize, SM2);
    cudaFuncSetAttribute(gemm_fp16<2,1>, cudaFuncAttributeMaxDynamicSharedMemorySize, SM2);

    const size_t WSLICE = (size_t)Dm * Pm;
    dim3 tblk(32, 8);

    // 1) weights -> W^T hi/lo (fp16)
    tsplit_f32<<<dim3(Pm/32, Dm/32, 1), tblk>>>(Wq, wthi + 0*WSLICE, wtlo + 0*WSLICE, Dm, Pm, 0, 0);
    tsplit_f32<<<dim3(Pm/32, Dm/32, 1), tblk>>>(Wk, wthi + 1*WSLICE, wtlo + 1*WSLICE, Dm, Pm, 0, 0);
    tsplit_f32<<<dim3(Pm/32, Dm/32, 1), tblk>>>(Wv, wthi + 2*WSLICE, wtlo + 2*WSLICE, Dm, Pm, 0, 0);
    tsplit_f32<<<dim3(Dm/32, Pm/32, 1), tblk>>>(Wo, wthi + 3*WSLICE, wtlo + 3*WSLICE, Pm, Dm, 0, 0);

    // 2) split x -> fp16 hi/lo
    {
        size_t n4 = (size_t)Mrows * Dm / 4;
        split_f32<<<(unsigned)((n4 + 255) / 256), 256>>>((const float4*)x, xhi, xlo, n4);
    }

    dim3 gProj(Pm / 128, Mrows / 128, 1);      // (4,128,1)
    dim3 gScore(Sseq / 128, Sseq / 128, Bsz);  // (32,32,4)
    dim3 gAV(Pm / 128, Sseq / 128, Bsz);       // (4,32,4)

    // 3) q = x @ Wq^T + bq   (3-term, write qhi only)
    gemm_fp16<3,2><<<gProj, 256, SM3>>>(xhi, xlo, wthi + 0*WSLICE, wtlo + 0*WSLICE,
                                        bq, nullptr, qhi, nullptr, Dm, 1.0f, 0, 0, 0);

    // 4) k = x @ Wk^T + bk   (3-term, write khi+klo)
    gemm_fp16<3,1><<<gProj, 256, SM3>>>(xhi, xlo, wthi + 1*WSLICE, wtlo + 1*WSLICE,
                                        bk, nullptr, khi, klo, Dm, 1.0f, 0, 0, 0);

    // 5) v = x @ Wv^T + bv   (3-term, fp32) then transpose-split per batch
    gemm_fp16<3,0><<<gProj, 256, SM3>>>(xhi, xlo, wthi + 2*WSLICE, wtlo + 2*WSLICE,
                                        bv, tmpf, nullptr, nullptr, Dm, 1.0f, 0, 0, 0);
    tsplit_f32<<<dim3(Pm/32, Sseq/32, Bsz), tblk>>>(tmpf, vthi, vtlo, Sseq, Pm,
                                                    (size_t)Sseq * Pm, (size_t)Sseq * Pm);

    // 6) scores = (q @ k^T) / 8   (2-term: qhi*khi + qhi*klo), fp32 out
    gemm_fp16<2,0><<<gScore, 256, SM2>>>(qhi, nullptr, khi, klo,
                                         nullptr, sc, nullptr, nullptr,
                                         Pm, 0.125f,
                                         (size_t)Sseq * Pm, (size_t)Sseq * Pm,
                                         (size_t)Sseq * Sseq);

    // 7) softmax -> fp16 probs
    softmax_probs<<<Bsz * Sseq, 256>>>(sc, phi);

    // 8) att = probs @ v   (2-term: phi*vhi + phi*vlo), write atthi+attlo
    gemm_fp16<2,1><<<gAV, 256, SM2>>>(phi, nullptr, vthi, vtlo,
                                      nullptr, nullptr, atthi, attlo,
                                      Sseq, 1.0f,
                                      (size_t)Sseq * Sseq, (size_t)Pm * Sseq,
                                      (size_t)Sseq * Pm);

    // 9) out = att @ Wo^T + bo   (3-term, fp32)
    gemm_fp16<3,0><<<gProj, 256, SM3>>>(atthi, attlo, wthi + 3*WSLICE, wtlo + 3*WSLICE,
                                        bo, out, nullptr, nullptr, Pm, 1.0f, 0, 0, 0);
}

// round 6
// speedup vs baseline: 5.2527x; 1.3652x over previous
#include <cuda_runtime.h>
#include <cuda_fp16.h>
#include <cstdint>
#include <math.h>

// ============================================================================
// CustomAttentionLayer on GB300 (sm_103 PTX target -> mma.sync HMMA path).
// Round 5: pure-fp16 attention GEMMs.
//   Projections / out-proj (3-term): Ahi*Bhi + Ahi*Blo + Alo*Bhi
//   Scores (1-term):  qhi*khi          Probs@V (1-term): phi*vhi
// 4-stage cp.async pipeline; 2 CTAs/SM on 1-term kernels.
// ============================================================================

#define Bsz 4
#define Sseq 4096
#define Dm 512
#define Pm 512
#define Mrows (Bsz * Sseq)   // 16384

// ---------------------------------------------------------------------------
// Scratch (device globals)
// ---------------------------------------------------------------------------
__device__ float  g_tmpf [Mrows * Pm];              // fp32 staging (v only)
__device__ __half g_xhi  [Mrows * Dm];
__device__ __half g_xlo  [Mrows * Dm];
__device__ __half g_qhi  [Mrows * Pm];
__device__ __half g_khi  [Mrows * Pm];
__device__ __half g_vthi [Mrows * Pm];              // v^T [B][P][S]
__device__ __half g_atthi[Mrows * Pm];
__device__ __half g_attlo[Mrows * Pm];
__device__ __half g_wthi [4 * Dm * Pm];             // Wq^T,Wk^T,Wv^T,Wo^T hi
__device__ __half g_wtlo [4 * Dm * Pm];
__device__ float  g_sc   [(size_t)Bsz * Sseq * Sseq];  // 256 MB scores fp32
__device__ __half g_phi  [(size_t)Bsz * Sseq * Sseq];  // 128 MB probs fp16

// ---------------------------------------------------------------------------
// PTX primitives
// ---------------------------------------------------------------------------
__device__ __forceinline__ uint32_t smem_u32(const void* p) {
    uint32_t a;
    asm("{ .reg .u64 t; cvta.to.shared.u64 t, %1; cvt.u32.u64 %0, t; }"
        : "=r"(a) : "l"(p));
    return a;
}
__device__ __forceinline__ void cp16(uint32_t dst, const void* src) {
    asm volatile("cp.async.cg.shared.global [%0], [%1], 16;" :: "r"(dst), "l"(src));
}
#define CP_COMMIT() asm volatile("cp.async.commit_group;" ::: "memory")
#define CP_WAIT(N)  asm volatile("cp.async.wait_group %0;" :: "n"(N) : "memory")

__device__ __forceinline__ void ldsm_x4(uint32_t* r, uint32_t addr) {
    asm volatile("ldmatrix.sync.aligned.m8n8.x4.shared.b16 {%0,%1,%2,%3}, [%4];"
                 : "=r"(r[0]), "=r"(r[1]), "=r"(r[2]), "=r"(r[3]) : "r"(addr));
}
__device__ __forceinline__ void mma16816(float* c, const uint32_t* a, const uint32_t* b) {
    asm volatile(
        "mma.sync.aligned.m16n8k16.row.col.f32.f16.f16.f32 "
        "{%0,%1,%2,%3}, {%4,%5,%6,%7}, {%8,%9}, {%0,%1,%2,%3};"
        : "+f"(c[0]), "+f"(c[1]), "+f"(c[2]), "+f"(c[3])
        : "r"(a[0]), "r"(a[1]), "r"(a[2]), "r"(a[3]), "r"(b[0]), "r"(b[1]));
}

// Swizzled offset inside a 128x32 fp16 tile (64B rows, 4x 16B chunks per row).
__device__ __forceinline__ uint32_t swoff(int r, int c) {
    return (uint32_t)(r * 64 + (((c ^ (r + (r >> 2))) & 3) << 4));
}

// ---------------------------------------------------------------------------
// GEMM: C[M,N] = alpha*(A @ B^T)(+bias); A[M,K], B[N,K] K-major fp16 hi/lo.
// TERMS: 3 -> Ahi*Bhi + Ahi*Blo + Alo*Bhi
//        2 -> Ahi*Bhi + Ahi*Blo
//        1 -> Ahi*Bhi
// OUTMODE: 0 -> fp32 Cf ; 1 -> fp16 Chi+Clo ; 2 -> fp16 Chi only
// 128x128 CTA tile, BK=32, 8 warps (2m x 4n), 4-stage cp.async pipeline.
// TERMS<=2: 2 CTAs/SM. TERMS==3: 1 CTA/SM.
// ---------------------------------------------------------------------------
#define BK 32
#define TILE_B 8192                 // 128 x 32 x 2B
#define NSTAGES 4

__device__ __forceinline__ void load_tile(uint32_t sbase, const __half* g,
                                          int ldk, int k0, int tid)
{
#pragma unroll
    for (int p = 0; p < 2; p++) {
        int f = tid + p * 256;
        int r = f >> 2;
        int c = f & 3;
        cp16(sbase + swoff(r, c), g + (size_t)r * ldk + k0 + c * 8);
    }
}

template <int TERMS, int OUTMODE>
__global__ __launch_bounds__(256, (TERMS <= 2) ? 2 : 1)
void gemm_fp16(const __half* __restrict__ Ahi, const __half* __restrict__ Alo,
               const __half* __restrict__ Bhi, const __half* __restrict__ Blo,
               const float* __restrict__ bias,
               float* __restrict__ Cf, __half* __restrict__ Chi, __half* __restrict__ Clo,
               int K, float alpha, size_t sA, size_t sB, size_t sC)
{
    constexpr int NTILES = (TERMS == 3) ? 4 : ((TERMS == 2) ? 3 : 2);
    constexpr int BUF_B  = NTILES * TILE_B;        // bytes per stage

    extern __shared__ char dynsmem[];
    const uint32_t sm0 = smem_u32(dynsmem);

    const int tid = threadIdx.x;
    const int wid = tid >> 5;
    const int lid = tid & 31;
    const int wm  = wid & 1;
    const int wn  = wid >> 1;
    const int N   = gridDim.x * 128;
    const int bm  = blockIdx.y * 128;
    const int bn  = blockIdx.x * 128;

    Ahi += (size_t)blockIdx.z * sA;
    if (TERMS == 3) Alo += (size_t)blockIdx.z * sA;
    Bhi += (size_t)blockIdx.z * sB;
    if (TERMS >= 2) Blo += (size_t)blockIdx.z * sB;

    const __half* tAhi = Ahi + (size_t)bm * K;
    const __half* tAlo = (TERMS == 3) ? (Alo + (size_t)bm * K) : nullptr;
    const __half* tBhi = Bhi + (size_t)bn * K;
    const __half* tBlo = (TERMS >= 2) ? (Blo + (size_t)bn * K) : nullptr;

    float acc[4][4][4];
#pragma unroll
    for (int i = 0; i < 4; i++)
#pragma unroll
        for (int j = 0; j < 4; j++)
#pragma unroll
            for (int e = 0; e < 4; e++) acc[i][j][e] = 0.f;

    const int NC = K / BK;

    // prologue: issue stages 0..NSTAGES-2
#pragma unroll
    for (int s = 0; s < NSTAGES - 1; s++) {
        if (s < NC) {
            uint32_t b = sm0 + s * BUF_B;
            const int k0 = s * BK;
            load_tile(b + 0 * TILE_B, tAhi, K, k0, tid);
            load_tile(b + 1 * TILE_B, tBhi, K, k0, tid);
            if (TERMS >= 2) load_tile(b + 2 * TILE_B, tBlo, K, k0, tid);
            if (TERMS == 3) load_tile(b + 3 * TILE_B, tAlo, K, k0, tid);
        }
        CP_COMMIT();
    }

    for (int c = 0; c < NC; c++) {
        CP_WAIT(NSTAGES - 2);
        __syncthreads();

        // issue stage c+NSTAGES-1
        {
            const int ps = c + NSTAGES - 1;
            if (ps < NC) {
                uint32_t b = sm0 + (ps % NSTAGES) * BUF_B;
                const int k0 = ps * BK;
                load_tile(b + 0 * TILE_B, tAhi, K, k0, tid);
                load_tile(b + 1 * TILE_B, tBhi, K, k0, tid);
                if (TERMS >= 2) load_tile(b + 2 * TILE_B, tBlo, K, k0, tid);
                if (TERMS == 3) load_tile(b + 3 * TILE_B, tAlo, K, k0, tid);
            }
            CP_COMMIT();
        }

        const uint32_t bb  = sm0 + (c % NSTAGES) * BUF_B;
        const uint32_t sAh = bb + 0 * TILE_B;
        const uint32_t sBh = bb + 1 * TILE_B;
        const uint32_t sBl = bb + 2 * TILE_B;
        const uint32_t sAl = bb + 3 * TILE_B;

#pragma unroll
        for (int ks = 0; ks < 2; ks++) {
            uint32_t ah[4][4], al[4][4], bh[4][2], bl[4][2];

            const int rA = wm * 64 + (lid & 15);
            const int cA = ks * 2 + (lid >> 4);
#pragma unroll
            for (int i = 0; i < 4; i++) {
                uint32_t off = swoff(rA + i * 16, cA);
                ldsm_x4(ah[i], sAh + off);
                if (TERMS == 3) ldsm_x4(al[i], sAl + off);
            }

            const int cB = ks * 2 + ((lid >> 3) & 1);
#pragma unroll
            for (int jp = 0; jp < 2; jp++) {
                const int rB = wn * 32 + jp * 16 + ((lid >> 4) & 1) * 8 + (lid & 7);
                uint32_t off = swoff(rB, cB);
                uint32_t t[4];
                ldsm_x4(t, sBh + off);
                bh[jp * 2][0] = t[0]; bh[jp * 2][1] = t[1];
                bh[jp * 2 + 1][0] = t[2]; bh[jp * 2 + 1][1] = t[3];
                if (TERMS >= 2) {
                    ldsm_x4(t, sBl + off);
                    bl[jp * 2][0] = t[0]; bl[jp * 2][1] = t[1];
                    bl[jp * 2 + 1][0] = t[2]; bl[jp * 2 + 1][1] = t[3];
                }
            }

#pragma unroll
            for (int i = 0; i < 4; i++)
#pragma unroll
                for (int j = 0; j < 4; j++) {
                    mma16816(acc[i][j], ah[i], bh[j]);
                    if (TERMS >= 2) mma16816(acc[i][j], ah[i], bl[j]);
                    if (TERMS == 3) mma16816(acc[i][j], al[i], bh[j]);
                }
        }
    }

    // epilogue
    const int mrow = bm + wm * 64 + (lid >> 2);
    const int ncol = bn + wn * 32 + 2 * (lid & 3);
#pragma unroll
    for (int i = 0; i < 4; i++) {
#pragma unroll
        for (int j = 0; j < 4; j++) {
            const int row = mrow + i * 16;
            const int col = ncol + j * 8;
            float v[4];
            v[0] = acc[i][j][0] * alpha;  v[1] = acc[i][j][1] * alpha;
            v[2] = acc[i][j][2] * alpha;  v[3] = acc[i][j][3] * alpha;
            if (bias) {
                const float2 bv = *(const float2*)&bias[col];
                v[0] += bv.x; v[1] += bv.y;
                v[2] += bv.x; v[3] += bv.y;
            }
            if (OUTMODE == 0) {
                float* Cz = Cf + (size_t)blockIdx.z * sC;
                *(float2*)&Cz[(size_t)row * N + col]       = make_float2(v[0], v[1]);
                *(float2*)&Cz[(size_t)(row + 8) * N + col] = make_float2(v[2], v[3]);
            } else {
                __half* Hz = Chi + (size_t)blockIdx.z * sC;
                __half h0 = __float2half_rn(v[0]);
                __half h1 = __float2half_rn(v[1]);
                __half h2 = __float2half_rn(v[2]);
                __half h3 = __float2half_rn(v[3]);
                *(__half2*)&Hz[(size_t)row * N + col]       = __halves2half2(h0, h1);
                *(__half2*)&Hz[(size_t)(row + 8) * N + col] = __halves2half2(h2, h3);
                if (OUTMODE == 1) {
                    __half* Lz = Clo + (size_t)blockIdx.z * sC;
                    __half l0 = __float2half_rn(v[0] - __half2float(h0));
                    __half l1 = __float2half_rn(v[1] - __half2float(h1));
                    __half l2 = __float2half_rn(v[2] - __half2float(h2));
                    __half l3 = __float2half_rn(v[3] - __half2float(h3));
                    *(__half2*)&Lz[(size_t)row * N + col]       = __halves2half2(l0, l1);
                    *(__half2*)&Lz[(size_t)(row + 8) * N + col] = __halves2half2(l2, l3);
                }
            }
        }
    }
}

// ---------------------------------------------------------------------------
// Elementwise split: fp32 -> (hi, lo) fp16
// ---------------------------------------------------------------------------
__global__ __launch_bounds__(256)
void split_f32(const float4* __restrict__ in, __half* __restrict__ hi,
               __half* __restrict__ lo, size_t n4)
{
    size_t i = (size_t)blockIdx.x * 256 + threadIdx.x;
    if (i >= n4) return;
    float4 v = in[i];
    float f[4] = {v.x, v.y, v.z, v.w};
    __half h[4], l[4];
#pragma unroll
    for (int j = 0; j < 4; j++) {
        h[j] = __float2half_rn(f[j]);
        l[j] = __float2half_rn(f[j] - __half2float(h[j]));
    }
    *(uint2*)(hi + i * 4) = *(uint2*)h;
    *(uint2*)(lo + i * 4) = *(uint2*)l;
}

// ---------------------------------------------------------------------------
// Transposed split: fp32 [R,C] -> hi (and optional lo) fp16 [C,R]
// ---------------------------------------------------------------------------
__global__ __launch_bounds__(256)
void tsplit_f32(const float* __restrict__ in, __half* __restrict__ hi,
                __half* __restrict__ lo, int R, int C,
                size_t sin, size_t sout)
{
    __shared__ float t[32][33];
    in += (size_t)blockIdx.z * sin;
    hi += (size_t)blockIdx.z * sout;
    if (lo) lo += (size_t)blockIdx.z * sout;
    int c0 = blockIdx.x * 32, r0 = blockIdx.y * 32;
    int tx = threadIdx.x, ty = threadIdx.y;
#pragma unroll
    for (int i = 0; i < 32; i += 8)
        t[ty + i][tx] = in[(size_t)(r0 + ty + i) * C + c0 + tx];
    __syncthreads();
#pragma unroll
    for (int i = 0; i < 32; i += 8) {
        float v = t[tx][ty + i];
        __half h = __float2half_rn(v);
        size_t o = (size_t)(c0 + ty + i) * R + r0 + tx;
        hi[o] = h;
        if (lo) lo[o] = __float2half_rn(v - __half2float(h));
    }
}

// ---------------------------------------------------------------------------
// Fused softmax: read fp32 scores row, write fp16 probs
// ---------------------------------------------------------------------------
__device__ __forceinline__ float warpMax(float v) {
#pragma unroll
    for (int o = 16; o; o >>= 1) v = fmaxf(v, __shfl_xor_sync(0xffffffffu, v, o));
    return v;
}
__device__ __forceinline__ float warpSum(float v) {
#pragma unroll
    for (int o = 16; o; o >>= 1) v += __shfl_xor_sync(0xffffffffu, v, o);
    return v;
}

__global__ __launch_bounds__(256)
void softmax_probs(const float* __restrict__ S, __half* __restrict__ P)
{
    const float* p = S + (size_t)blockIdx.x * 4096;
    __half* ph     = P + (size_t)blockIdx.x * 4096;
    __shared__ float sred[8];
    __shared__ float sbcast;

    float4 v[4];
    float mx = -3.0e38f;
#pragma unroll
    for (int l = 0; l < 4; l++) {
        v[l] = *(const float4*)&p[(threadIdx.x + l * 256) * 4];
        mx = fmaxf(mx, fmaxf(fmaxf(v[l].x, v[l].y), fmaxf(v[l].z, v[l].w)));
    }
    mx = warpMax(mx);
    if ((threadIdx.x & 31) == 0) sred[threadIdx.x >> 5] = mx;
    __syncthreads();
    if (threadIdx.x < 32) {
        float t = (threadIdx.x < 8) ? sred[threadIdx.x] : -3.0e38f;
        t = warpMax(t);
        if (threadIdx.x == 0) sbcast = t;
    }
    __syncthreads();
    mx = sbcast;
    __syncthreads();

    float sum = 0.f;
#pragma unroll
    for (int l = 0; l < 4; l++) {
        v[l].x = __expf(v[l].x - mx);
        v[l].y = __expf(v[l].y - mx);
        v[l].z = __expf(v[l].z - mx);
        v[l].w = __expf(v[l].w - mx);
        sum += v[l].x + v[l].y + v[l].z + v[l].w;
    }
    sum = warpSum(sum);
    if ((threadIdx.x & 31) == 0) sred[threadIdx.x >> 5] = sum;
    __syncthreads();
    if (threadIdx.x < 32) {
        float t = (threadIdx.x < 8) ? sred[threadIdx.x] : 0.f;
        t = warpSum(t);
        if (threadIdx.x == 0) sbcast = t;
    }
    __syncthreads();
    float inv = 1.f / sbcast;

#pragma unroll
    for (int l = 0; l < 4; l++) {
        __half2 a = __floats2half2_rn(v[l].x * inv, v[l].y * inv);
        __half2 b = __floats2half2_rn(v[l].z * inv, v[l].w * inv);
        uint2 u;
        u.x = *(uint32_t*)&a;
        u.y = *(uint32_t*)&b;
        *(uint2*)&ph[(threadIdx.x + l * 256) * 4] = u;
    }
}

// ---------------------------------------------------------------------------
// kernel_launch
// ---------------------------------------------------------------------------
extern "C" void kernel_launch(void* const* d_in, const int* in_sizes, int n_in,
                              void* d_out, int out_size)
{
    (void)in_sizes; (void)n_in; (void)out_size;
    const float* x  = (const float*)d_in[0];
    const float* Wq = (const float*)d_in[1];
    const float* bq = (const float*)d_in[2];
    const float* Wk = (const float*)d_in[3];
    const float* bk = (const float*)d_in[4];
    const float* Wv = (const float*)d_in[5];
    const float* bv = (const float*)d_in[6];
    const float* Wo = (const float*)d_in[7];
    const float* bo = (const float*)d_in[8];
    float* out = (float*)d_out;

    float *tmpf, *sc;
    __half *xhi, *xlo, *qhi, *khi, *vthi;
    __half *atthi, *attlo, *wthi, *wtlo, *phi;
    cudaGetSymbolAddress((void**)&tmpf,  g_tmpf);
    cudaGetSymbolAddress((void**)&sc,    g_sc);
    cudaGetSymbolAddress((void**)&xhi,   g_xhi);
    cudaGetSymbolAddress((void**)&xlo,   g_xlo);
    cudaGetSymbolAddress((void**)&qhi,   g_qhi);
    cudaGetSymbolAddress((void**)&khi,   g_khi);
    cudaGetSymbolAddress((void**)&vthi,  g_vthi);
    cudaGetSymbolAddress((void**)&atthi, g_atthi);
    cudaGetSymbolAddress((void**)&attlo, g_attlo);
    cudaGetSymbolAddress((void**)&wthi,  g_wthi);
    cudaGetSymbolAddress((void**)&wtlo,  g_wtlo);
    cudaGetSymbolAddress((void**)&phi,   g_phi);

    const int SM3 = NSTAGES * 4 * TILE_B;   // 128 KB (3-term, 1 CTA/SM)
    const int SM1 = NSTAGES * 2 * TILE_B;   // 64 KB  (1-term, 2 CTAs/SM)
    cudaFuncSetAttribute(gemm_fp16<3,0>, cudaFuncAttributeMaxDynamicSharedMemorySize, SM3);
    cudaFuncSetAttribute(gemm_fp16<3,1>, cudaFuncAttributeMaxDynamicSharedMemorySize, SM3);
    cudaFuncSetAttribute(gemm_fp16<3,2>, cudaFuncAttributeMaxDynamicSharedMemorySize, SM3);
    cudaFuncSetAttribute(gemm_fp16<1,0>, cudaFuncAttributeMaxDynamicSharedMemorySize, SM1);
    cudaFuncSetAttribute(gemm_fp16<1,1>, cudaFuncAttributeMaxDynamicSharedMemorySize, SM1);

    const size_t WSLICE = (size_t)Dm * Pm;
    dim3 tblk(32, 8);

    // 1) weights -> W^T hi/lo (fp16)
    tsplit_f32<<<dim3(Pm/32, Dm/32, 1), tblk>>>(Wq, wthi + 0*WSLICE, wtlo + 0*WSLICE, Dm, Pm, 0, 0);
    tsplit_f32<<<dim3(Pm/32, Dm/32, 1), tblk>>>(Wk, wthi + 1*WSLICE, wtlo + 1*WSLICE, Dm, Pm, 0, 0);
    tsplit_f32<<<dim3(Pm/32, Dm/32, 1), tblk>>>(Wv, wthi + 2*WSLICE, wtlo + 2*WSLICE, Dm, Pm, 0, 0);
    tsplit_f32<<<dim3(Dm/32, Pm/32, 1), tblk>>>(Wo, wthi + 3*WSLICE, wtlo + 3*WSLICE, Pm, Dm, 0, 0);

    // 2) split x -> fp16 hi/lo
    {
        size_t n4 = (size_t)Mrows * Dm / 4;
        split_f32<<<(unsigned)((n4 + 255) / 256), 256>>>((const float4*)x, xhi, xlo, n4);
    }

    dim3 gProj(Pm / 128, Mrows / 128, 1);      // (4,128,1)
    dim3 gScore(Sseq / 128, Sseq / 128, Bsz);  // (32,32,4)
    dim3 gAV(Pm / 128, Sseq / 128, Bsz);       // (4,32,4)

    // 3) q = x @ Wq^T + bq   (3-term, write qhi only)
    gemm_fp16<3,2><<<gProj, 256, SM3>>>(xhi, xlo, wthi + 0*WSLICE, wtlo + 0*WSLICE,
                                        bq, nullptr, qhi, nullptr, Dm, 1.0f, 0, 0, 0);

    // 4) k = x @ Wk^T + bk   (3-term, write khi only)
    gemm_fp16<3,2><<<gProj, 256, SM3>>>(xhi, xlo, wthi + 1*WSLICE, wtlo + 1*WSLICE,
                                        bk, nullptr, khi, nullptr, Dm, 1.0f, 0, 0, 0);

    // 5) v = x @ Wv^T + bv   (3-term, fp32) then transpose (hi only) per batch
    gemm_fp16<3,0><<<gProj, 256, SM3>>>(xhi, xlo, wthi + 2*WSLICE, wtlo + 2*WSLICE,
                                        bv, tmpf, nullptr, nullptr, Dm, 1.0f, 0, 0, 0);
    tsplit_f32<<<dim3(Pm/32, Sseq/32, Bsz), tblk>>>(tmpf, vthi, nullptr, Sseq, Pm,
                                                    (size_t)Sseq * Pm, (size_t)Sseq * Pm);

    // 6) scores = (q @ k^T) / 8   (1-term fp16), fp32 out
    gemm_fp16<1,0><<<gScore, 256, SM1>>>(qhi, nullptr, khi, nullptr,
                                         nullptr, sc, nullptr, nullptr,
                                         Pm, 0.125f,
                                         (size_t)Sseq * Pm, (size_t)Sseq * Pm,
                                         (size_t)Sseq * Sseq);

    // 7) softmax -> fp16 probs
    softmax_probs<<<Bsz * Sseq, 256>>>(sc, phi);

    // 8) att = probs @ v   (1-term fp16), write atthi+attlo
    gemm_fp16<1,1><<<gAV, 256, SM1>>>(phi, nullptr, vthi, nullptr,
                                      nullptr, nullptr, atthi, attlo,
                                      Sseq, 1.0f,
                                      (size_t)Sseq * Sseq, (size_t)Pm * Sseq,
                                      (size_t)Sseq * Pm);

    // 9) out = att @ Wo^T + bo   (3-term, fp32)
    gemm_fp16<3,0><<<gProj, 256, SM3>>>(atthi, attlo, wthi + 3*WSLICE, wtlo + 3*WSLICE,
                                        bo, out, nullptr, nullptr, Pm, 1.0f, 0, 0, 0);
}

// round 7
// speedup vs baseline: 6.3450x; 1.2079x over previous
#include <cuda_runtime.h>
#include <cuda_fp16.h>
#include <cstdint>
#include <math.h>

// ============================================================================
// CustomAttentionLayer on GB300 (sm_103 PTX target -> mma.sync HMMA path).
// Round 6:
//   - fused QKV projection: ONE 2-term GEMM (xhi only), N=1536, fp16-hi out
//   - scores GEMM epilogue writes exp(s/8) fp16 (no max-sub, no softmax pass)
//   - rowsum kernel + normalization folded into PV epilogue
//   - out-projection stays 3-term, fp32 out
// ============================================================================

#define Bsz 4
#define Sseq 4096
#define Dm 512
#define Pm 512
#define Mrows (Bsz * Sseq)   // 16384
#define QKVN 1536

// ---------------------------------------------------------------------------
// Scratch (device globals)
// ---------------------------------------------------------------------------
__device__ __half g_xhi  [Mrows * Dm];
__device__ __half g_qkv  [(size_t)Mrows * QKVN];    // [16384, 1536] q|k|v fp16
__device__ __half g_vthi [Mrows * Pm];              // v^T [B][P][S]
__device__ __half g_atthi[Mrows * Pm];
__device__ __half g_attlo[Mrows * Pm];
__device__ __half g_wthi [4 * Dm * Pm];             // Wq^T,Wk^T,Wv^T,Wo^T hi
__device__ __half g_wtlo [4 * Dm * Pm];
__device__ float  g_bqkv [QKVN];                    // concat bq|bk|bv
__device__ __half g_phi  [(size_t)Bsz * Sseq * Sseq];  // 128 MB exp-probs fp16
__device__ float  g_rowsum[Mrows];                  // per-row sum of exp

// ---------------------------------------------------------------------------
// PTX primitives
// ---------------------------------------------------------------------------
__device__ __forceinline__ uint32_t smem_u32(const void* p) {
    uint32_t a;
    asm("{ .reg .u64 t; cvta.to.shared.u64 t, %1; cvt.u32.u64 %0, t; }"
        : "=r"(a) : "l"(p));
    return a;
}
__device__ __forceinline__ void cp16(uint32_t dst, const void* src) {
    asm volatile("cp.async.cg.shared.global [%0], [%1], 16;" :: "r"(dst), "l"(src));
}
#define CP_COMMIT() asm volatile("cp.async.commit_group;" ::: "memory")
#define CP_WAIT(N)  asm volatile("cp.async.wait_group %0;" :: "n"(N) : "memory")

__device__ __forceinline__ void ldsm_x4(uint32_t* r, uint32_t addr) {
    asm volatile("ldmatrix.sync.aligned.m8n8.x4.shared.b16 {%0,%1,%2,%3}, [%4];"
                 : "=r"(r[0]), "=r"(r[1]), "=r"(r[2]), "=r"(r[3]) : "r"(addr));
}
__device__ __forceinline__ void mma16816(float* c, const uint32_t* a, const uint32_t* b) {
    asm volatile(
        "mma.sync.aligned.m16n8k16.row.col.f32.f16.f16.f32 "
        "{%0,%1,%2,%3}, {%4,%5,%6,%7}, {%8,%9}, {%0,%1,%2,%3};"
        : "+f"(c[0]), "+f"(c[1]), "+f"(c[2]), "+f"(c[3])
        : "r"(a[0]), "r"(a[1]), "r"(a[2]), "r"(a[3]), "r"(b[0]), "r"(b[1]));
}

// Swizzled offset inside a 128x32 fp16 tile (64B rows, 4x 16B chunks per row).
__device__ __forceinline__ uint32_t swoff(int r, int c) {
    return (uint32_t)(r * 64 + (((c ^ (r + (r >> 2))) & 3) << 4));
}

// ---------------------------------------------------------------------------
// GEMM: C[M,N] = f(alpha*(A @ B^T)(+bias)); A[M,K] (ldA), B[N,K] (ldB), fp16.
// TERMS: 3 -> Ahi*Bhi + Ahi*Blo + Alo*Bhi ; 2 -> Ahi*Bhi + Ahi*Blo ; 1 -> Ahi*Bhi
// OUTMODE: 0 fp32 ; 1 fp16 hi+lo (optional 1/rowsum scale) ; 2 fp16 hi ; 3 fp16 exp()
// 128x128 CTA tile, BK=32, 8 warps (2m x 4n), 4-stage cp.async pipeline.
// TERMS<=2: 2 CTAs/SM. TERMS==3: 1 CTA/SM.
// ---------------------------------------------------------------------------
#define BK 32
#define TILE_B 8192                 // 128 x 32 x 2B
#define NSTAGES 4

__device__ __forceinline__ void load_tile(uint32_t sbase, const __half* g,
                                          int ldk, int k0, int tid)
{
#pragma unroll
    for (int p = 0; p < 2; p++) {
        int f = tid + p * 256;
        int r = f >> 2;
        int c = f & 3;
        cp16(sbase + swoff(r, c), g + (size_t)r * ldk + k0 + c * 8);
    }
}

template <int TERMS, int OUTMODE>
__global__ __launch_bounds__(256, (TERMS <= 2) ? 2 : 1)
void gemm_fp16(const __half* __restrict__ Ahi, const __half* __restrict__ Alo,
               const __half* __restrict__ Bhi, const __half* __restrict__ Blo,
               const float* __restrict__ bias, const float* __restrict__ rowsum,
               float* __restrict__ Cf, __half* __restrict__ Chi, __half* __restrict__ Clo,
               int K, int ldA, int ldB, float alpha, size_t sA, size_t sB, size_t sC)
{
    constexpr int NTILES = (TERMS == 3) ? 4 : ((TERMS == 2) ? 3 : 2);
    constexpr int BUF_B  = NTILES * TILE_B;

    extern __shared__ char dynsmem[];
    const uint32_t sm0 = smem_u32(dynsmem);

    const int tid = threadIdx.x;
    const int wid = tid >> 5;
    const int lid = tid & 31;
    const int wm  = wid & 1;
    const int wn  = wid >> 1;
    const int N   = gridDim.x * 128;
    const int Mb  = gridDim.y * 128;     // rows per batch slice
    const int bm  = blockIdx.y * 128;
    const int bn  = blockIdx.x * 128;

    Ahi += (size_t)blockIdx.z * sA;
    if (TERMS == 3) Alo += (size_t)blockIdx.z * sA;
    Bhi += (size_t)blockIdx.z * sB;
    if (TERMS >= 2) Blo += (size_t)blockIdx.z * sB;

    const __half* tAhi = Ahi + (size_t)bm * ldA;
    const __half* tAlo = (TERMS == 3) ? (Alo + (size_t)bm * ldA) : nullptr;
    const __half* tBhi = Bhi + (size_t)bn * ldB;
    const __half* tBlo = (TERMS >= 2) ? (Blo + (size_t)bn * ldB) : nullptr;

    float acc[4][4][4];
#pragma unroll
    for (int i = 0; i < 4; i++)
#pragma unroll
        for (int j = 0; j < 4; j++)
#pragma unroll
            for (int e = 0; e < 4; e++) acc[i][j][e] = 0.f;

    const int NC = K / BK;

#pragma unroll
    for (int s = 0; s < NSTAGES - 1; s++) {
        if (s < NC) {
            uint32_t b = sm0 + s * BUF_B;
            const int k0 = s * BK;
            load_tile(b + 0 * TILE_B, tAhi, ldA, k0, tid);
            load_tile(b + 1 * TILE_B, tBhi, ldB, k0, tid);
            if (TERMS >= 2) load_tile(b + 2 * TILE_B, tBlo, ldB, k0, tid);
            if (TERMS == 3) load_tile(b + 3 * TILE_B, tAlo, ldA, k0, tid);
        }
        CP_COMMIT();
    }

    for (int c = 0; c < NC; c++) {
        CP_WAIT(NSTAGES - 2);
        __syncthreads();

        {
            const int ps = c + NSTAGES - 1;
            if (ps < NC) {
                uint32_t b = sm0 + (ps % NSTAGES) * BUF_B;
                const int k0 = ps * BK;
                load_tile(b + 0 * TILE_B, tAhi, ldA, k0, tid);
                load_tile(b + 1 * TILE_B, tBhi, ldB, k0, tid);
                if (TERMS >= 2) load_tile(b + 2 * TILE_B, tBlo, ldB, k0, tid);
                if (TERMS == 3) load_tile(b + 3 * TILE_B, tAlo, ldA, k0, tid);
            }
            CP_COMMIT();
        }

        const uint32_t bb  = sm0 + (c % NSTAGES) * BUF_B;
        const uint32_t sAh = bb + 0 * TILE_B;
        const uint32_t sBh = bb + 1 * TILE_B;
        const uint32_t sBl = bb + 2 * TILE_B;
        const uint32_t sAl = bb + 3 * TILE_B;

#pragma unroll
        for (int ks = 0; ks < 2; ks++) {
            uint32_t ah[4][4], al[4][4], bh[4][2], bl[4][2];

            const int rA = wm * 64 + (lid & 15);
            const int cA = ks * 2 + (lid >> 4);
#pragma unroll
            for (int i = 0; i < 4; i++) {
                uint32_t off = swoff(rA + i * 16, cA);
                ldsm_x4(ah[i], sAh + off);
                if (TERMS == 3) ldsm_x4(al[i], sAl + off);
            }

            const int cB = ks * 2 + ((lid >> 3) & 1);
#pragma unroll
            for (int jp = 0; jp < 2; jp++) {
                const int rB = wn * 32 + jp * 16 + ((lid >> 4) & 1) * 8 + (lid & 7);
                uint32_t off = swoff(rB, cB);
                uint32_t t[4];
                ldsm_x4(t, sBh + off);
                bh[jp * 2][0] = t[0]; bh[jp * 2][1] = t[1];
                bh[jp * 2 + 1][0] = t[2]; bh[jp * 2 + 1][1] = t[3];
                if (TERMS >= 2) {
                    ldsm_x4(t, sBl + off);
                    bl[jp * 2][0] = t[0]; bl[jp * 2][1] = t[1];
                    bl[jp * 2 + 1][0] = t[2]; bl[jp * 2 + 1][1] = t[3];
                }
            }

#pragma unroll
            for (int i = 0; i < 4; i++)
#pragma unroll
                for (int j = 0; j < 4; j++) {
                    mma16816(acc[i][j], ah[i], bh[j]);
                    if (TERMS >= 2) mma16816(acc[i][j], ah[i], bl[j]);
                    if (TERMS == 3) mma16816(acc[i][j], al[i], bh[j]);
                }
        }
    }

    // epilogue
    const int mrow = bm + wm * 64 + (lid >> 2);
    const int ncol = bn + wn * 32 + 2 * (lid & 3);
#pragma unroll
    for (int i = 0; i < 4; i++) {
        const int row  = mrow + i * 16;
        float inv0 = 1.f, inv1 = 1.f;
        if (OUTMODE == 1 && rowsum) {
            inv0 = 1.f / rowsum[(size_t)blockIdx.z * Mb + row];
            inv1 = 1.f / rowsum[(size_t)blockIdx.z * Mb + row + 8];
        }
#pragma unroll
        for (int j = 0; j < 4; j++) {
            const int col = ncol + j * 8;
            float v[4];
            v[0] = acc[i][j][0] * alpha;  v[1] = acc[i][j][1] * alpha;
            v[2] = acc[i][j][2] * alpha;  v[3] = acc[i][j][3] * alpha;
            if (bias) {
                const float2 bv = *(const float2*)&bias[col];
                v[0] += bv.x; v[1] += bv.y;
                v[2] += bv.x; v[3] += bv.y;
            }
            if (OUTMODE == 0) {
                float* Cz = Cf + (size_t)blockIdx.z * sC;
                *(float2*)&Cz[(size_t)row * N + col]       = make_float2(v[0], v[1]);
                *(float2*)&Cz[(size_t)(row + 8) * N + col] = make_float2(v[2], v[3]);
            } else if (OUTMODE == 3) {
                __half* Hz = Chi + (size_t)blockIdx.z * sC;
                __half2 e0 = __floats2half2_rn(__expf(v[0]), __expf(v[1]));
                __half2 e1 = __floats2half2_rn(__expf(v[2]), __expf(v[3]));
                *(__half2*)&Hz[(size_t)row * N + col]       = e0;
                *(__half2*)&Hz[(size_t)(row + 8) * N + col] = e1;
            } else {
                if (OUTMODE == 1 && rowsum) {
                    v[0] *= inv0; v[1] *= inv0; v[2] *= inv1; v[3] *= inv1;
                }
                __half* Hz = Chi + (size_t)blockIdx.z * sC;
                __half h0 = __float2half_rn(v[0]);
                __half h1 = __float2half_rn(v[1]);
                __half h2 = __float2half_rn(v[2]);
                __half h3 = __float2half_rn(v[3]);
                *(__half2*)&Hz[(size_t)row * N + col]       = __halves2half2(h0, h1);
                *(__half2*)&Hz[(size_t)(row + 8) * N + col] = __halves2half2(h2, h3);
                if (OUTMODE == 1) {
                    __half* Lz = Clo + (size_t)blockIdx.z * sC;
                    __half l0 = __float2half_rn(v[0] - __half2float(h0));
                    __half l1 = __float2half_rn(v[1] - __half2float(h1));
                    __half l2 = __float2half_rn(v[2] - __half2float(h2));
                    __half l3 = __float2half_rn(v[3] - __half2float(h3));
                    *(__half2*)&Lz[(size_t)row * N + col]       = __halves2half2(l0, l1);
                    *(__half2*)&Lz[(size_t)(row + 8) * N + col] = __halves2half2(l2, l3);
                }
            }
        }
    }
}

// ---------------------------------------------------------------------------
// x -> fp16 (hi only)
// ---------------------------------------------------------------------------
__global__ __launch_bounds__(256)
void conv_f32_f16(const float4* __restrict__ in, __half* __restrict__ hi, size_t n4)
{
    size_t i = (size_t)blockIdx.x * 256 + threadIdx.x;
    if (i >= n4) return;
    float4 v = in[i];
    __half2 a = __floats2half2_rn(v.x, v.y);
    __half2 b = __floats2half2_rn(v.z, v.w);
    uint2 u; u.x = *(uint32_t*)&a; u.y = *(uint32_t*)&b;
    *(uint2*)(hi + i * 4) = u;
}

// ---------------------------------------------------------------------------
// Weight transposed split: fp32 [R,C] -> hi/lo fp16 [C,R]
// ---------------------------------------------------------------------------
__global__ __launch_bounds__(256)
void tsplit_f32(const float* __restrict__ in, __half* __restrict__ hi,
                __half* __restrict__ lo, int R, int C)
{
    __shared__ float t[32][33];
    int c0 = blockIdx.x * 32, r0 = blockIdx.y * 32;
    int tx = threadIdx.x, ty = threadIdx.y;
#pragma unroll
    for (int i = 0; i < 32; i += 8)
        t[ty + i][tx] = in[(size_t)(r0 + ty + i) * C + c0 + tx];
    __syncthreads();
#pragma unroll
    for (int i = 0; i < 32; i += 8) {
        float v = t[tx][ty + i];
        __half h = __float2half_rn(v);
        size_t o = (size_t)(c0 + ty + i) * R + r0 + tx;
        hi[o] = h;
        lo[o] = __float2half_rn(v - __half2float(h));
    }
}

// ---------------------------------------------------------------------------
// fp16 transpose: v slice of g_qkv [per batch 4096 x 512, ld 1536] -> [512, 4096]
// ---------------------------------------------------------------------------
__global__ __launch_bounds__(256)
void transpose_f16(const __half* __restrict__ in, __half* __restrict__ out,
                   int R, int C, int ldin, size_t sin, size_t sout)
{
    __shared__ __half t[32][33];
    in  += (size_t)blockIdx.z * sin;
    out += (size_t)blockIdx.z * sout;
    int c0 = blockIdx.x * 32, r0 = blockIdx.y * 32;
    int tx = threadIdx.x, ty = threadIdx.y;
#pragma unroll
    for (int i = 0; i < 32; i += 8)
        t[ty + i][tx] = in[(size_t)(r0 + ty + i) * ldin + c0 + tx];
    __syncthreads();
#pragma unroll
    for (int i = 0; i < 32; i += 8)
        out[(size_t)(c0 + ty + i) * R + r0 + tx] = t[tx][ty + i];
}

// ---------------------------------------------------------------------------
// bias concat: g_bqkv = [bq | bk | bv]
// ---------------------------------------------------------------------------
__global__ void concat_bias(const float* bq, const float* bk, const float* bv,
                            float* dst)
{
    int i = blockIdx.x * 256 + threadIdx.x;
    if (i < 512)        dst[i] = bq[i];
    else if (i < 1024)  dst[i] = bk[i - 512];
    else if (i < 1536)  dst[i] = bv[i - 1024];
}

// ---------------------------------------------------------------------------
// Row sums of exp-probs: 16384 rows x 4096 fp16 -> fp32
// ---------------------------------------------------------------------------
__global__ __launch_bounds__(128)
void rowsum_f16(const __half* __restrict__ P, float* __restrict__ S)
{
    const __half* p = P + (size_t)blockIdx.x * 4096;
    float sum = 0.f;
#pragma unroll
    for (int l = 0; l < 2; l++) {
        uint4 u = *(const uint4*)&p[(threadIdx.x + l * 128) * 16];
        const __half2* h = (const __half2*)&u;
#pragma unroll
        for (int j = 0; j < 4; j++) {
            float2 f = __half22float2(h[j]);
            sum += f.x + f.y;
        }
        uint4 u2 = *(const uint4*)&p[(threadIdx.x + l * 128) * 16 + 8];
        const __half2* h2 = (const __half2*)&u2;
#pragma unroll
        for (int j = 0; j < 4; j++) {
            float2 f = __half22float2(h2[j]);
            sum += f.x + f.y;
        }
    }
#pragma unroll
    for (int o = 16; o; o >>= 1) sum += __shfl_xor_sync(0xffffffffu, sum, o);
    __shared__ float sred[4];
    if ((threadIdx.x & 31) == 0) sred[threadIdx.x >> 5] = sum;
    __syncthreads();
    if (threadIdx.x == 0)
        S[blockIdx.x] = sred[0] + sred[1] + sred[2] + sred[3];
}

// ---------------------------------------------------------------------------
// kernel_launch
// ---------------------------------------------------------------------------
extern "C" void kernel_launch(void* const* d_in, const int* in_sizes, int n_in,
                              void* d_out, int out_size)
{
    (void)in_sizes; (void)n_in; (void)out_size;
    const float* x  = (const float*)d_in[0];
    const float* Wq = (const float*)d_in[1];
    const float* bq = (const float*)d_in[2];
    const float* Wk = (const float*)d_in[3];
    const float* bk = (const float*)d_in[4];
    const float* Wv = (const float*)d_in[5];
    const float* bv = (const float*)d_in[6];
    const float* Wo = (const float*)d_in[7];
    const float* bo = (const float*)d_in[8];
    float* out = (float*)d_out;

    __half *xhi, *qkv, *vthi, *atthi, *attlo, *wthi, *wtlo, *phi;
    float *bqkv, *rowsum;
    cudaGetSymbolAddress((void**)&xhi,    g_xhi);
    cudaGetSymbolAddress((void**)&qkv,    g_qkv);
    cudaGetSymbolAddress((void**)&vthi,   g_vthi);
    cudaGetSymbolAddress((void**)&atthi,  g_atthi);
    cudaGetSymbolAddress((void**)&attlo,  g_attlo);
    cudaGetSymbolAddress((void**)&wthi,   g_wthi);
    cudaGetSymbolAddress((void**)&wtlo,   g_wtlo);
    cudaGetSymbolAddress((void**)&bqkv,   g_bqkv);
    cudaGetSymbolAddress((void**)&phi,    g_phi);
    cudaGetSymbolAddress((void**)&rowsum, g_rowsum);

    const int SM3 = NSTAGES * 4 * TILE_B;   // 128 KB (3-term, 1 CTA/SM)
    const int SM2 = NSTAGES * 3 * TILE_B;   // 96 KB  (2-term, 2 CTAs/SM)
    const int SM1 = NSTAGES * 2 * TILE_B;   // 64 KB  (1-term, 2 CTAs/SM)
    cudaFuncSetAttribute(gemm_fp16<3,0>, cudaFuncAttributeMaxDynamicSharedMemorySize, SM3);
    cudaFuncSetAttribute(gemm_fp16<2,2>, cudaFuncAttributeMaxDynamicSharedMemorySize, SM2);
    cudaFuncSetAttribute(gemm_fp16<1,3>, cudaFuncAttributeMaxDynamicSharedMemorySize, SM1);
    cudaFuncSetAttribute(gemm_fp16<1,1>, cudaFuncAttributeMaxDynamicSharedMemorySize, SM1);

    const size_t WSLICE = (size_t)Dm * Pm;
    dim3 tblk(32, 8);

    // 1) weights -> W^T hi/lo (Wq,Wk,Wv slices contiguous => concatenated B)
    tsplit_f32<<<dim3(Pm/32, Dm/32, 1), tblk>>>(Wq, wthi + 0*WSLICE, wtlo + 0*WSLICE, Dm, Pm);
    tsplit_f32<<<dim3(Pm/32, Dm/32, 1), tblk>>>(Wk, wthi + 1*WSLICE, wtlo + 1*WSLICE, Dm, Pm);
    tsplit_f32<<<dim3(Pm/32, Dm/32, 1), tblk>>>(Wv, wthi + 2*WSLICE, wtlo + 2*WSLICE, Dm, Pm);
    tsplit_f32<<<dim3(Dm/32, Pm/32, 1), tblk>>>(Wo, wthi + 3*WSLICE, wtlo + 3*WSLICE, Pm, Dm);
    concat_bias<<<6, 256>>>(bq, bk, bv, bqkv);

    // 2) x -> fp16 hi
    {
        size_t n4 = (size_t)Mrows * Dm / 4;
        conv_f32_f16<<<(unsigned)((n4 + 255) / 256), 256>>>((const float4*)x, xhi, n4);
    }

    // 3) fused QKV: [16384,1536] = x @ [Wq|Wk|Wv]^T + b  (2-term, fp16-hi out)
    {
        dim3 g(QKVN / 128, Mrows / 128, 1);   // (12,128,1)
        gemm_fp16<2,2><<<g, 256, SM2>>>(xhi, nullptr, wthi, wtlo,
                                        bqkv, nullptr, nullptr, qkv, nullptr,
                                        Dm, Dm, Dm, 1.0f, 0, 0, (size_t)Mrows * QKVN);
        // note: sC unused pattern — C has blockIdx.z=0 only; stride irrelevant
    }

    // 4) v transpose (fp16): per batch [4096,512] (ld 1536) -> [512,4096]
    transpose_f16<<<dim3(Pm/32, Sseq/32, Bsz), tblk>>>(
        qkv + 1024, vthi, Sseq, Pm, QKVN,
        (size_t)Sseq * QKVN, (size_t)Pm * Sseq);

    // 5) exp-scores = exp((q @ k^T)/8) fp16   (1-term)
    {
        dim3 g(Sseq / 128, Sseq / 128, Bsz);  // (32,32,4)
        gemm_fp16<1,3><<<g, 256, SM1>>>(qkv + 0, nullptr, qkv + 512, nullptr,
                                        nullptr, nullptr, nullptr, phi, nullptr,
                                        Pm, QKVN, QKVN, 0.125f,
                                        (size_t)Sseq * QKVN, (size_t)Sseq * QKVN,
                                        (size_t)Sseq * Sseq);
    }

    // 6) row sums of exp-probs
    rowsum_f16<<<Mrows, 128>>>(phi, rowsum);

    // 7) att = (exp-probs @ v) / rowsum   (1-term, fp16 hi+lo out)
    {
        dim3 g(Pm / 128, Sseq / 128, Bsz);    // (4,32,4)
        gemm_fp16<1,1><<<g, 256, SM1>>>(phi, nullptr, vthi, nullptr,
                                        nullptr, rowsum, nullptr, atthi, attlo,
                                        Sseq, Sseq, Sseq, 1.0f,
                                        (size_t)Sseq * Sseq, (size_t)Pm * Sseq,
                                        (size_t)Sseq * Pm);
    }

    // 8) out = att @ Wo^T + bo   (3-term, fp32)
    {
        dim3 g(Dm / 128, Mrows / 128, 1);     // (4,128,1)
        gemm_fp16<3,0><<<g, 256, SM3>>>(atthi, attlo, wthi + 3*WSLICE, wtlo + 3*WSLICE,
                                        bo, nullptr, out, nullptr, nullptr,
                                        Pm, Pm, Pm, 1.0f, 0, 0, 0);
    }
}

// round 8
// speedup vs baseline: 6.7010x; 1.0561x over previous
#include <cuda_runtime.h>
#include <cuda_fp16.h>
#include <cstdint>
#include <math.h>

// ============================================================================
// CustomAttentionLayer on GB300 (sm_103 PTX target -> mma.sync HMMA path).
// Round 7: 64x64 warp tiles (4 warps/CTA, 128 threads), same math as R6:
//   - fused QKV projection: ONE 2-term GEMM (xhi only), N=1536, fp16-hi out
//   - scores epilogue writes exp(s/8) fp16 (no softmax pass)
//   - rowsum kernel + normalization folded into PV epilogue
//   - out-projection 3-term, fp32 out
// ============================================================================

#define Bsz 4
#define Sseq 4096
#define Dm 512
#define Pm 512
#define Mrows (Bsz * Sseq)   // 16384
#define QKVN 1536

// ---------------------------------------------------------------------------
// Scratch (device globals)
// ---------------------------------------------------------------------------
__device__ __half g_xhi  [Mrows * Dm];
__device__ __half g_qkv  [(size_t)Mrows * QKVN];    // [16384, 1536] q|k|v fp16
__device__ __half g_vthi [Mrows * Pm];              // v^T [B][P][S]
__device__ __half g_atthi[Mrows * Pm];
__device__ __half g_attlo[Mrows * Pm];
__device__ __half g_wthi [4 * Dm * Pm];             // Wq^T,Wk^T,Wv^T,Wo^T hi
__device__ __half g_wtlo [4 * Dm * Pm];
__device__ float  g_bqkv [QKVN];                    // concat bq|bk|bv
__device__ __half g_phi  [(size_t)Bsz * Sseq * Sseq];  // 128 MB exp-probs fp16
__device__ float  g_rowsum[Mrows];                  // per-row sum of exp

// ---------------------------------------------------------------------------
// PTX primitives
// ---------------------------------------------------------------------------
__device__ __forceinline__ uint32_t smem_u32(const void* p) {
    uint32_t a;
    asm("{ .reg .u64 t; cvta.to.shared.u64 t, %1; cvt.u32.u64 %0, t; }"
        : "=r"(a) : "l"(p));
    return a;
}
__device__ __forceinline__ void cp16(uint32_t dst, const void* src) {
    asm volatile("cp.async.cg.shared.global [%0], [%1], 16;" :: "r"(dst), "l"(src));
}
#define CP_COMMIT() asm volatile("cp.async.commit_group;" ::: "memory")
#define CP_WAIT(N)  asm volatile("cp.async.wait_group %0;" :: "n"(N) : "memory")

__device__ __forceinline__ void ldsm_x4(uint32_t* r, uint32_t addr) {
    asm volatile("ldmatrix.sync.aligned.m8n8.x4.shared.b16 {%0,%1,%2,%3}, [%4];"
                 : "=r"(r[0]), "=r"(r[1]), "=r"(r[2]), "=r"(r[3]) : "r"(addr));
}
__device__ __forceinline__ void mma16816(float* c, const uint32_t* a, const uint32_t* b) {
    asm volatile(
        "mma.sync.aligned.m16n8k16.row.col.f32.f16.f16.f32 "
        "{%0,%1,%2,%3}, {%4,%5,%6,%7}, {%8,%9}, {%0,%1,%2,%3};"
        : "+f"(c[0]), "+f"(c[1]), "+f"(c[2]), "+f"(c[3])
        : "r"(a[0]), "r"(a[1]), "r"(a[2]), "r"(a[3]), "r"(b[0]), "r"(b[1]));
}

// Swizzled offset inside a 128x32 fp16 tile (64B rows, 4x 16B chunks per row).
__device__ __forceinline__ uint32_t swoff(int r, int c) {
    return (uint32_t)(r * 64 + (((c ^ (r + (r >> 2))) & 3) << 4));
}

// ---------------------------------------------------------------------------
// GEMM: C[M,N] = f(alpha*(A @ B^T)(+bias)); A[M,K] (ldA), B[N,K] (ldB), fp16.
// TERMS: 3 -> Ahi*Bhi + Ahi*Blo + Alo*Bhi ; 2 -> Ahi*Bhi + Ahi*Blo ; 1 -> Ahi*Bhi
// OUTMODE: 0 fp32 ; 1 fp16 hi+lo (optional 1/rowsum) ; 2 fp16 hi ; 3 fp16 exp()
// 128x128 CTA tile, BK=32, 4 warps (2m x 2n), warp tile 64x64,
// 4-stage cp.async pipeline. TERMS<=2: 2 CTAs/SM. TERMS==3: 1 CTA/SM.
// ---------------------------------------------------------------------------
#define BK 32
#define TILE_B 8192                 // 128 x 32 x 2B
#define NSTAGES 4
#define NTHR 128

__device__ __forceinline__ void load_tile(uint32_t sbase, const __half* g,
                                          int ldk, int k0, int tid)
{
#pragma unroll
    for (int p = 0; p < 4; p++) {
        int f = tid + p * NTHR;           // 0..511 16B chunks
        int r = f >> 2;
        int c = f & 3;
        cp16(sbase + swoff(r, c), g + (size_t)r * ldk + k0 + c * 8);
    }
}

template <int TERMS, int OUTMODE>
__global__ __launch_bounds__(NTHR, (TERMS <= 2) ? 2 : 1)
void gemm_fp16(const __half* __restrict__ Ahi, const __half* __restrict__ Alo,
               const __half* __restrict__ Bhi, const __half* __restrict__ Blo,
               const float* __restrict__ bias, const float* __restrict__ rowsum,
               float* __restrict__ Cf, __half* __restrict__ Chi, __half* __restrict__ Clo,
               int K, int ldA, int ldB, float alpha, size_t sA, size_t sB, size_t sC)
{
    constexpr int NTILES = (TERMS == 3) ? 4 : ((TERMS == 2) ? 3 : 2);
    constexpr int BUF_B  = NTILES * TILE_B;

    extern __shared__ char dynsmem[];
    const uint32_t sm0 = smem_u32(dynsmem);

    const int tid = threadIdx.x;
    const int wid = tid >> 5;
    const int lid = tid & 31;
    const int wm  = wid & 1;          // 0..1 (64-row slab)
    const int wn  = wid >> 1;         // 0..1 (64-col slab)
    const int N   = gridDim.x * 128;
    const int Mb  = gridDim.y * 128;
    const int bm  = blockIdx.y * 128;
    const int bn  = blockIdx.x * 128;

    Ahi += (size_t)blockIdx.z * sA;
    if (TERMS == 3) Alo += (size_t)blockIdx.z * sA;
    Bhi += (size_t)blockIdx.z * sB;
    if (TERMS >= 2) Blo += (size_t)blockIdx.z * sB;

    const __half* tAhi = Ahi + (size_t)bm * ldA;
    const __half* tAlo = (TERMS == 3) ? (Alo + (size_t)bm * ldA) : nullptr;
    const __half* tBhi = Bhi + (size_t)bn * ldB;
    const __half* tBlo = (TERMS >= 2) ? (Blo + (size_t)bn * ldB) : nullptr;

    float acc[4][8][4];
#pragma unroll
    for (int i = 0; i < 4; i++)
#pragma unroll
        for (int j = 0; j < 8; j++)
#pragma unroll
            for (int e = 0; e < 4; e++) acc[i][j][e] = 0.f;

    const int NC = K / BK;

#pragma unroll
    for (int s = 0; s < NSTAGES - 1; s++) {
        if (s < NC) {
            uint32_t b = sm0 + s * BUF_B;
            const int k0 = s * BK;
            load_tile(b + 0 * TILE_B, tAhi, ldA, k0, tid);
            load_tile(b + 1 * TILE_B, tBhi, ldB, k0, tid);
            if (TERMS >= 2) load_tile(b + 2 * TILE_B, tBlo, ldB, k0, tid);
            if (TERMS == 3) load_tile(b + 3 * TILE_B, tAlo, ldA, k0, tid);
        }
        CP_COMMIT();
    }

    for (int c = 0; c < NC; c++) {
        CP_WAIT(NSTAGES - 2);
        __syncthreads();

        {
            const int ps = c + NSTAGES - 1;
            if (ps < NC) {
                uint32_t b = sm0 + (ps % NSTAGES) * BUF_B;
                const int k0 = ps * BK;
                load_tile(b + 0 * TILE_B, tAhi, ldA, k0, tid);
                load_tile(b + 1 * TILE_B, tBhi, ldB, k0, tid);
                if (TERMS >= 2) load_tile(b + 2 * TILE_B, tBlo, ldB, k0, tid);
                if (TERMS == 3) load_tile(b + 3 * TILE_B, tAlo, ldA, k0, tid);
            }
            CP_COMMIT();
        }

        const uint32_t bb  = sm0 + (c % NSTAGES) * BUF_B;
        const uint32_t sAh = bb + 0 * TILE_B;
        const uint32_t sBh = bb + 1 * TILE_B;
        const uint32_t sBl = bb + 2 * TILE_B;
        const uint32_t sAl = bb + 3 * TILE_B;

#pragma unroll
        for (int ks = 0; ks < 2; ks++) {
            uint32_t ah[4][4], al[4][4], bh[8][2], bl[8][2];

            const int rA = wm * 64 + (lid & 15);
            const int cA = ks * 2 + (lid >> 4);
#pragma unroll
            for (int i = 0; i < 4; i++) {
                uint32_t off = swoff(rA + i * 16, cA);
                ldsm_x4(ah[i], sAh + off);
                if (TERMS == 3) ldsm_x4(al[i], sAl + off);
            }

            const int cB = ks * 2 + ((lid >> 3) & 1);
#pragma unroll
            for (int jp = 0; jp < 4; jp++) {
                const int rB = wn * 64 + jp * 16 + ((lid >> 4) & 1) * 8 + (lid & 7);
                uint32_t off = swoff(rB, cB);
                uint32_t t[4];
                ldsm_x4(t, sBh + off);
                bh[jp * 2][0] = t[0]; bh[jp * 2][1] = t[1];
                bh[jp * 2 + 1][0] = t[2]; bh[jp * 2 + 1][1] = t[3];
                if (TERMS >= 2) {
                    ldsm_x4(t, sBl + off);
                    bl[jp * 2][0] = t[0]; bl[jp * 2][1] = t[1];
                    bl[jp * 2 + 1][0] = t[2]; bl[jp * 2 + 1][1] = t[3];
                }
            }

#pragma unroll
            for (int i = 0; i < 4; i++)
#pragma unroll
                for (int j = 0; j < 8; j++) {
                    mma16816(acc[i][j], ah[i], bh[j]);
                    if (TERMS >= 2) mma16816(acc[i][j], ah[i], bl[j]);
                    if (TERMS == 3) mma16816(acc[i][j], al[i], bh[j]);
                }
        }
    }

    // epilogue
    const int mrow = bm + wm * 64 + (lid >> 2);
    const int ncol = bn + wn * 64 + 2 * (lid & 3);
#pragma unroll
    for (int i = 0; i < 4; i++) {
        const int row = mrow + i * 16;
        float inv0 = 1.f, inv1 = 1.f;
        if (OUTMODE == 1 && rowsum) {
            inv0 = 1.f / rowsum[(size_t)blockIdx.z * Mb + row];
            inv1 = 1.f / rowsum[(size_t)blockIdx.z * Mb + row + 8];
        }
#pragma unroll
        for (int j = 0; j < 8; j++) {
            const int col = ncol + j * 8;
            float v[4];
            v[0] = acc[i][j][0] * alpha;  v[1] = acc[i][j][1] * alpha;
            v[2] = acc[i][j][2] * alpha;  v[3] = acc[i][j][3] * alpha;
            if (bias) {
                const float2 bv = *(const float2*)&bias[col];
                v[0] += bv.x; v[1] += bv.y;
                v[2] += bv.x; v[3] += bv.y;
            }
            if (OUTMODE == 0) {
                float* Cz = Cf + (size_t)blockIdx.z * sC;
                *(float2*)&Cz[(size_t)row * N + col]       = make_float2(v[0], v[1]);
                *(float2*)&Cz[(size_t)(row + 8) * N + col] = make_float2(v[2], v[3]);
            } else if (OUTMODE == 3) {
                __half* Hz = Chi + (size_t)blockIdx.z * sC;
                __half2 e0 = __floats2half2_rn(__expf(v[0]), __expf(v[1]));
                __half2 e1 = __floats2half2_rn(__expf(v[2]), __expf(v[3]));
                *(__half2*)&Hz[(size_t)row * N + col]       = e0;
                *(__half2*)&Hz[(size_t)(row + 8) * N + col] = e1;
            } else {
                if (OUTMODE == 1 && rowsum) {
                    v[0] *= inv0; v[1] *= inv0; v[2] *= inv1; v[3] *= inv1;
                }
                __half* Hz = Chi + (size_t)blockIdx.z * sC;
                __half h0 = __float2half_rn(v[0]);
                __half h1 = __float2half_rn(v[1]);
                __half h2 = __float2half_rn(v[2]);
                __half h3 = __float2half_rn(v[3]);
                *(__half2*)&Hz[(size_t)row * N + col]       = __halves2half2(h0, h1);
                *(__half2*)&Hz[(size_t)(row + 8) * N + col] = __halves2half2(h2, h3);
                if (OUTMODE == 1) {
                    __half* Lz = Clo + (size_t)blockIdx.z * sC;
                    __half l0 = __float2half_rn(v[0] - __half2float(h0));
                    __half l1 = __float2half_rn(v[1] - __half2float(h1));
                    __half l2 = __float2half_rn(v[2] - __half2float(h2));
                    __half l3 = __float2half_rn(v[3] - __half2float(h3));
                    *(__half2*)&Lz[(size_t)row * N + col]       = __halves2half2(l0, l1);
                    *(__half2*)&Lz[(size_t)(row + 8) * N + col] = __halves2half2(l2, l3);
                }
            }
        }
    }
}

// ---------------------------------------------------------------------------
// x -> fp16 (hi only)
// ---------------------------------------------------------------------------
__global__ __launch_bounds__(256)
void conv_f32_f16(const float4* __restrict__ in, __half* __restrict__ hi, size_t n4)
{
    size_t i = (size_t)blockIdx.x * 256 + threadIdx.x;
    if (i >= n4) return;
    float4 v = in[i];
    __half2 a = __floats2half2_rn(v.x, v.y);
    __half2 b = __floats2half2_rn(v.z, v.w);
    uint2 u; u.x = *(uint32_t*)&a; u.y = *(uint32_t*)&b;
    *(uint2*)(hi + i * 4) = u;
}

// ---------------------------------------------------------------------------
// Weight transposed split: fp32 [R,C] -> hi/lo fp16 [C,R]
// ---------------------------------------------------------------------------
__global__ __launch_bounds__(256)
void tsplit_f32(const float* __restrict__ in, __half* __restrict__ hi,
                __half* __restrict__ lo, int R, int C)
{
    __shared__ float t[32][33];
    int c0 = blockIdx.x * 32, r0 = blockIdx.y * 32;
    int tx = threadIdx.x, ty = threadIdx.y;
#pragma unroll
    for (int i = 0; i < 32; i += 8)
        t[ty + i][tx] = in[(size_t)(r0 + ty + i) * C + c0 + tx];
    __syncthreads();
#pragma unroll
    for (int i = 0; i < 32; i += 8) {
        float v = t[tx][ty + i];
        __half h = __float2half_rn(v);
        size_t o = (size_t)(c0 + ty + i) * R + r0 + tx;
        hi[o] = h;
        lo[o] = __float2half_rn(v - __half2float(h));
    }
}

// ---------------------------------------------------------------------------
// fp16 transpose: v slice of g_qkv [per batch 4096 x 512, ld 1536] -> [512, 4096]
// ---------------------------------------------------------------------------
__global__ __launch_bounds__(256)
void transpose_f16(const __half* __restrict__ in, __half* __restrict__ out,
                   int R, int C, int ldin, size_t sin, size_t sout)
{
    __shared__ __half t[32][33];
    in  += (size_t)blockIdx.z * sin;
    out += (size_t)blockIdx.z * sout;
    int c0 = blockIdx.x * 32, r0 = blockIdx.y * 32;
    int tx = threadIdx.x, ty = threadIdx.y;
#pragma unroll
    for (int i = 0; i < 32; i += 8)
        t[ty + i][tx] = in[(size_t)(r0 + ty + i) * ldin + c0 + tx];
    __syncthreads();
#pragma unroll
    for (int i = 0; i < 32; i += 8)
        out[(size_t)(c0 + ty + i) * R + r0 + tx] = t[tx][ty + i];
}

// ---------------------------------------------------------------------------
// bias concat: g_bqkv = [bq | bk | bv]
// ---------------------------------------------------------------------------
__global__ void concat_bias(const float* bq, const float* bk, const float* bv,
                            float* dst)
{
    int i = blockIdx.x * 256 + threadIdx.x;
    if (i < 512)        dst[i] = bq[i];
    else if (i < 1024)  dst[i] = bk[i - 512];
    else if (i < 1536)  dst[i] = bv[i - 1024];
}

// ---------------------------------------------------------------------------
// Row sums of exp-probs: 16384 rows x 4096 fp16 -> fp32
// ---------------------------------------------------------------------------
__global__ __launch_bounds__(128)
void rowsum_f16(const __half* __restrict__ P, float* __restrict__ S)
{
    const __half* p = P + (size_t)blockIdx.x * 4096;
    float sum = 0.f;
#pragma unroll
    for (int l = 0; l < 2; l++) {
        uint4 u = *(const uint4*)&p[(threadIdx.x + l * 128) * 16];
        const __half2* h = (const __half2*)&u;
#pragma unroll
        for (int j = 0; j < 4; j++) {
            float2 f = __half22float2(h[j]);
            sum += f.x + f.y;
        }
        uint4 u2 = *(const uint4*)&p[(threadIdx.x + l * 128) * 16 + 8];
        const __half2* h2 = (const __half2*)&u2;
#pragma unroll
        for (int j = 0; j < 4; j++) {
            float2 f = __half22float2(h2[j]);
            sum += f.x + f.y;
        }
    }
#pragma unroll
    for (int o = 16; o; o >>= 1) sum += __shfl_xor_sync(0xffffffffu, sum, o);
    __shared__ float sred[4];
    if ((threadIdx.x & 31) == 0) sred[threadIdx.x >> 5] = sum;
    __syncthreads();
    if (threadIdx.x == 0)
        S[blockIdx.x] = sred[0] + sred[1] + sred[2] + sred[3];
}

// ---------------------------------------------------------------------------
// kernel_launch
// ---------------------------------------------------------------------------
extern "C" void kernel_launch(void* const* d_in, const int* in_sizes, int n_in,
                              void* d_out, int out_size)
{
    (void)in_sizes; (void)n_in; (void)out_size;
    const float* x  = (const float*)d_in[0];
    const float* Wq = (const float*)d_in[1];
    const float* bq = (const float*)d_in[2];
    const float* Wk = (const float*)d_in[3];
    const float* bk = (const float*)d_in[4];
    const float* Wv = (const float*)d_in[5];
    const float* bv = (const float*)d_in[6];
    const float* Wo = (const float*)d_in[7];
    const float* bo = (const float*)d_in[8];
    float* out = (float*)d_out;

    __half *xhi, *qkv, *vthi, *atthi, *attlo, *wthi, *wtlo, *phi;
    float *bqkv, *rowsum;
    cudaGetSymbolAddress((void**)&xhi,    g_xhi);
    cudaGetSymbolAddress((void**)&qkv,    g_qkv);
    cudaGetSymbolAddress((void**)&vthi,   g_vthi);
    cudaGetSymbolAddress((void**)&atthi,  g_atthi);
    cudaGetSymbolAddress((void**)&attlo,  g_attlo);
    cudaGetSymbolAddress((void**)&wthi,   g_wthi);
    cudaGetSymbolAddress((void**)&wtlo,   g_wtlo);
    cudaGetSymbolAddress((void**)&bqkv,   g_bqkv);
    cudaGetSymbolAddress((void**)&phi,    g_phi);
    cudaGetSymbolAddress((void**)&rowsum, g_rowsum);

    const int SM3 = NSTAGES * 4 * TILE_B;   // 128 KB (3-term, 1 CTA/SM)
    const int SM2 = NSTAGES * 3 * TILE_B;   // 96 KB  (2-term, 2 CTAs/SM)
    const int SM1 = NSTAGES * 2 * TILE_B;   // 64 KB  (1-term, 2 CTAs/SM)
    cudaFuncSetAttribute(gemm_fp16<3,0>, cudaFuncAttributeMaxDynamicSharedMemorySize, SM3);
    cudaFuncSetAttribute(gemm_fp16<2,2>, cudaFuncAttributeMaxDynamicSharedMemorySize, SM2);
    cudaFuncSetAttribute(gemm_fp16<1,3>, cudaFuncAttributeMaxDynamicSharedMemorySize, SM1);
    cudaFuncSetAttribute(gemm_fp16<1,1>, cudaFuncAttributeMaxDynamicSharedMemorySize, SM1);

    const size_t WSLICE = (size_t)Dm * Pm;
    dim3 tblk(32, 8);

    // 1) weights -> W^T hi/lo (Wq,Wk,Wv slices contiguous => concatenated B)
    tsplit_f32<<<dim3(Pm/32, Dm/32, 1), tblk>>>(Wq, wthi + 0*WSLICE, wtlo + 0*WSLICE, Dm, Pm);
    tsplit_f32<<<dim3(Pm/32, Dm/32, 1), tblk>>>(Wk, wthi + 1*WSLICE, wtlo + 1*WSLICE, Dm, Pm);
    tsplit_f32<<<dim3(Pm/32, Dm/32, 1), tblk>>>(Wv, wthi + 2*WSLICE, wtlo + 2*WSLICE, Dm, Pm);
    tsplit_f32<<<dim3(Dm/32, Pm/32, 1), tblk>>>(Wo, wthi + 3*WSLICE, wtlo + 3*WSLICE, Pm, Dm);
    concat_bias<<<6, 256>>>(bq, bk, bv, bqkv);

    // 2) x -> fp16 hi
    {
        size_t n4 = (size_t)Mrows * Dm / 4;
        conv_f32_f16<<<(unsigned)((n4 + 255) / 256), 256>>>((const float4*)x, xhi, n4);
    }

    // 3) fused QKV: [16384,1536] = x @ [Wq|Wk|Wv]^T + b  (2-term, fp16-hi out)
    {
        dim3 g(QKVN / 128, Mrows / 128, 1);   // (12,128,1)
        gemm_fp16<2,2><<<g, NTHR, SM2>>>(xhi, nullptr, wthi, wtlo,
                                         bqkv, nullptr, nullptr, qkv, nullptr,
                                         Dm, Dm, Dm, 1.0f, 0, 0, (size_t)Mrows * QKVN);
    }

    // 4) v transpose (fp16): per batch [4096,512] (ld 1536) -> [512,4096]
    transpose_f16<<<dim3(Pm/32, Sseq/32, Bsz), tblk>>>(
        qkv + 1024, vthi, Sseq, Pm, QKVN,
        (size_t)Sseq * QKVN, (size_t)Pm * Sseq);

    // 5) exp-scores = exp((q @ k^T)/8) fp16   (1-term)
    {
        dim3 g(Sseq / 128, Sseq / 128, Bsz);  // (32,32,4)
        gemm_fp16<1,3><<<g, NTHR, SM1>>>(qkv + 0, nullptr, qkv + 512, nullptr,
                                         nullptr, nullptr, nullptr, phi, nullptr,
                                         Pm, QKVN, QKVN, 0.125f,
                                         (size_t)Sseq * QKVN, (size_t)Sseq * QKVN,
                                         (size_t)Sseq * Sseq);
    }

    // 6) row sums of exp-probs
    rowsum_f16<<<Mrows, 128>>>(phi, rowsum);

    // 7) att = (exp-probs @ v) / rowsum   (1-term, fp16 hi+lo out)
    {
        dim3 g(Pm / 128, Sseq / 128, Bsz);    // (4,32,4)
        gemm_fp16<1,1><<<g, NTHR, SM1>>>(phi, nullptr, vthi, nullptr,
                                         nullptr, rowsum, nullptr, atthi, attlo,
                                         Sseq, Sseq, Sseq, 1.0f,
                                         (size_t)Sseq * Sseq, (size_t)Pm * Sseq,
                                         (size_t)Sseq * Pm);
    }

    // 8) out = att @ Wo^T + bo   (3-term, fp32)
    {
        dim3 g(Dm / 128, Mrows / 128, 1);     // (4,128,1)
        gemm_fp16<3,0><<<g, NTHR, SM3>>>(atthi, attlo, wthi + 3*WSLICE, wtlo + 3*WSLICE,
                                         bo, nullptr, out, nullptr, nullptr,
                                         Pm, Pm, Pm, 1.0f, 0, 0, 0);
    }
}

// round 9
// speedup vs baseline: 8.3251x; 1.2424x over previous
#include <cuda_runtime.h>
#include <cuda_fp16.h>
#include <cstdint>
#include <math.h>

// ============================================================================
// CustomAttentionLayer on GB300 (sm_103 PTX target -> mma.sync HMMA path).
// Round 8:
//   - QKV projection 1-term (xhi * Whi) + bias, fp16-hi out
//   - scores epilogue writes exp(s/8) fp16 AND atomically accumulates rowsum
//   - PV 1-term, divides by rowsum, writes fp16 hi only
//   - out-projection 2-term (atthi*Wohi + atthi*Wolo), fp32 out, 2 CTAs/SM
// ============================================================================

#define Bsz 4
#define Sseq 4096
#define Dm 512
#define Pm 512
#define Mrows (Bsz * Sseq)   // 16384
#define QKVN 1536

// ---------------------------------------------------------------------------
// Scratch (device globals)
// ---------------------------------------------------------------------------
__device__ __half g_xhi  [Mrows * Dm];
__device__ __half g_qkv  [(size_t)Mrows * QKVN];    // [16384, 1536] q|k|v fp16
__device__ __half g_vthi [Mrows * Pm];              // v^T [B][P][S]
__device__ __half g_atthi[Mrows * Pm];
__device__ __half g_wthi [4 * Dm * Pm];             // Wq^T,Wk^T,Wv^T,Wo^T hi
__device__ __half g_wolo [Dm * Pm];                 // Wo^T lo only
__device__ float  g_bqkv [QKVN];                    // concat bq|bk|bv
__device__ __half g_phi  [(size_t)Bsz * Sseq * Sseq];  // 128 MB exp-probs fp16
__device__ float  g_rowsum[Mrows];                  // per-row sum of exp

// ---------------------------------------------------------------------------
// PTX primitives
// ---------------------------------------------------------------------------
__device__ __forceinline__ uint32_t smem_u32(const void* p) {
    uint32_t a;
    asm("{ .reg .u64 t; cvta.to.shared.u64 t, %1; cvt.u32.u64 %0, t; }"
        : "=r"(a) : "l"(p));
    return a;
}
__device__ __forceinline__ void cp16(uint32_t dst, const void* src) {
    asm volatile("cp.async.cg.shared.global [%0], [%1], 16;" :: "r"(dst), "l"(src));
}
#define CP_COMMIT() asm volatile("cp.async.commit_group;" ::: "memory")
#define CP_WAIT(N)  asm volatile("cp.async.wait_group %0;" :: "n"(N) : "memory")

__device__ __forceinline__ void ldsm_x4(uint32_t* r, uint32_t addr) {
    asm volatile("ldmatrix.sync.aligned.m8n8.x4.shared.b16 {%0,%1,%2,%3}, [%4];"
                 : "=r"(r[0]), "=r"(r[1]), "=r"(r[2]), "=r"(r[3]) : "r"(addr));
}
__device__ __forceinline__ void mma16816(float* c, const uint32_t* a, const uint32_t* b) {
    asm volatile(
        "mma.sync.aligned.m16n8k16.row.col.f32.f16.f16.f32 "
        "{%0,%1,%2,%3}, {%4,%5,%6,%7}, {%8,%9}, {%0,%1,%2,%3};"
        : "+f"(c[0]), "+f"(c[1]), "+f"(c[2]), "+f"(c[3])
        : "r"(a[0]), "r"(a[1]), "r"(a[2]), "r"(a[3]), "r"(b[0]), "r"(b[1]));
}

// Swizzled offset inside a 128x32 fp16 tile (64B rows, 4x 16B chunks per row).
__device__ __forceinline__ uint32_t swoff(int r, int c) {
    return (uint32_t)(r * 64 + (((c ^ (r + (r >> 2))) & 3) << 4));
}

// ---------------------------------------------------------------------------
// GEMM: C[M,N] = f(alpha*(A @ B^T)(+bias)); A[M,K] (ldA), B[N,K] (ldB), fp16.
// TERMS: 2 -> Ahi*Bhi + Ahi*Blo ; 1 -> Ahi*Bhi
// OUTMODE: 0 fp32 ; 2 fp16 hi (optional 1/rowsum scale) ;
//          3 fp16 exp() + atomic rowsum accumulation
// 128x128 CTA tile, BK=32, 4 warps (2m x 2n), warp tile 64x64,
// 4-stage cp.async pipeline, 2 CTAs/SM.
// ---------------------------------------------------------------------------
#define BK 32
#define TILE_B 8192                 // 128 x 32 x 2B
#define NSTAGES 4
#define NTHR 128

__device__ __forceinline__ void load_tile(uint32_t sbase, const __half* g,
                                          int ldk, int k0, int tid)
{
#pragma unroll
    for (int p = 0; p < 4; p++) {
        int f = tid + p * NTHR;           // 0..511 16B chunks
        int r = f >> 2;
        int c = f & 3;
        cp16(sbase + swoff(r, c), g + (size_t)r * ldk + k0 + c * 8);
    }
}

template <int TERMS, int OUTMODE>
__global__ __launch_bounds__(NTHR, 2)
void gemm_fp16(const __half* __restrict__ Ahi,
               const __half* __restrict__ Bhi, const __half* __restrict__ Blo,
               const float* __restrict__ bias, float* __restrict__ rowsum,
               float* __restrict__ Cf, __half* __restrict__ Chi,
               int K, int ldA, int ldB, float alpha, size_t sA, size_t sB, size_t sC)
{
    constexpr int NTILES = (TERMS == 2) ? 3 : 2;
    constexpr int BUF_B  = NTILES * TILE_B;

    extern __shared__ char dynsmem[];
    const uint32_t sm0 = smem_u32(dynsmem);

    const int tid = threadIdx.x;
    const int wid = tid >> 5;
    const int lid = tid & 31;
    const int wm  = wid & 1;          // 0..1 (64-row slab)
    const int wn  = wid >> 1;         // 0..1 (64-col slab)
    const int N   = gridDim.x * 128;
    const int Mb  = gridDim.y * 128;
    const int bm  = blockIdx.y * 128;
    const int bn  = blockIdx.x * 128;

    Ahi += (size_t)blockIdx.z * sA;
    Bhi += (size_t)blockIdx.z * sB;
    if (TERMS >= 2) Blo += (size_t)blockIdx.z * sB;

    const __half* tAhi = Ahi + (size_t)bm * ldA;
    const __half* tBhi = Bhi + (size_t)bn * ldB;
    const __half* tBlo = (TERMS >= 2) ? (Blo + (size_t)bn * ldB) : nullptr;

    float acc[4][8][4];
#pragma unroll
    for (int i = 0; i < 4; i++)
#pragma unroll
        for (int j = 0; j < 8; j++)
#pragma unroll
            for (int e = 0; e < 4; e++) acc[i][j][e] = 0.f;

    const int NC = K / BK;

#pragma unroll
    for (int s = 0; s < NSTAGES - 1; s++) {
        if (s < NC) {
            uint32_t b = sm0 + s * BUF_B;
            const int k0 = s * BK;
            load_tile(b + 0 * TILE_B, tAhi, ldA, k0, tid);
            load_tile(b + 1 * TILE_B, tBhi, ldB, k0, tid);
            if (TERMS >= 2) load_tile(b + 2 * TILE_B, tBlo, ldB, k0, tid);
        }
        CP_COMMIT();
    }

    for (int c = 0; c < NC; c++) {
        CP_WAIT(NSTAGES - 2);
        __syncthreads();

        {
            const int ps = c + NSTAGES - 1;
            if (ps < NC) {
                uint32_t b = sm0 + (ps % NSTAGES) * BUF_B;
                const int k0 = ps * BK;
                load_tile(b + 0 * TILE_B, tAhi, ldA, k0, tid);
                load_tile(b + 1 * TILE_B, tBhi, ldB, k0, tid);
                if (TERMS >= 2) load_tile(b + 2 * TILE_B, tBlo, ldB, k0, tid);
            }
            CP_COMMIT();
        }

        const uint32_t bb  = sm0 + (c % NSTAGES) * BUF_B;
        const uint32_t sAh = bb + 0 * TILE_B;
        const uint32_t sBh = bb + 1 * TILE_B;
        const uint32_t sBl = bb + 2 * TILE_B;

#pragma unroll
        for (int ks = 0; ks < 2; ks++) {
            uint32_t ah[4][4], bh[8][2], bl[8][2];

            const int rA = wm * 64 + (lid & 15);
            const int cA = ks * 2 + (lid >> 4);
#pragma unroll
            for (int i = 0; i < 4; i++) {
                uint32_t off = swoff(rA + i * 16, cA);
                ldsm_x4(ah[i], sAh + off);
            }

            const int cB = ks * 2 + ((lid >> 3) & 1);
#pragma unroll
            for (int jp = 0; jp < 4; jp++) {
                const int rB = wn * 64 + jp * 16 + ((lid >> 4) & 1) * 8 + (lid & 7);
                uint32_t off = swoff(rB, cB);
                uint32_t t[4];
                ldsm_x4(t, sBh + off);
                bh[jp * 2][0] = t[0]; bh[jp * 2][1] = t[1];
                bh[jp * 2 + 1][0] = t[2]; bh[jp * 2 + 1][1] = t[3];
                if (TERMS >= 2) {
                    ldsm_x4(t, sBl + off);
                    bl[jp * 2][0] = t[0]; bl[jp * 2][1] = t[1];
                    bl[jp * 2 + 1][0] = t[2]; bl[jp * 2 + 1][1] = t[3];
                }
            }

#pragma unroll
            for (int i = 0; i < 4; i++)
#pragma unroll
                for (int j = 0; j < 8; j++) {
                    mma16816(acc[i][j], ah[i], bh[j]);
                    if (TERMS >= 2) mma16816(acc[i][j], ah[i], bl[j]);
                }
        }
    }

    // epilogue
    const int mrow = bm + wm * 64 + (lid >> 2);
    const int ncol = bn + wn * 64 + 2 * (lid & 3);
#pragma unroll
    for (int i = 0; i < 4; i++) {
        const int row = mrow + i * 16;
        float inv0 = 1.f, inv1 = 1.f;
        if (OUTMODE == 2 && rowsum) {
            inv0 = 1.f / rowsum[(size_t)blockIdx.z * Mb + row];
            inv1 = 1.f / rowsum[(size_t)blockIdx.z * Mb + row + 8];
        }
        float sumA = 0.f, sumB = 0.f;   // OUTMODE 3 row partials
#pragma unroll
        for (int j = 0; j < 8; j++) {
            const int col = ncol + j * 8;
            float v[4];
            v[0] = acc[i][j][0] * alpha;  v[1] = acc[i][j][1] * alpha;
            v[2] = acc[i][j][2] * alpha;  v[3] = acc[i][j][3] * alpha;
            if (bias) {
                const float2 bv = *(const float2*)&bias[col];
                v[0] += bv.x; v[1] += bv.y;
                v[2] += bv.x; v[3] += bv.y;
            }
            if (OUTMODE == 0) {
                float* Cz = Cf + (size_t)blockIdx.z * sC;
                *(float2*)&Cz[(size_t)row * N + col]       = make_float2(v[0], v[1]);
                *(float2*)&Cz[(size_t)(row + 8) * N + col] = make_float2(v[2], v[3]);
            } else if (OUTMODE == 3) {
                float e0 = __expf(v[0]), e1 = __expf(v[1]);
                float e2 = __expf(v[2]), e3 = __expf(v[3]);
                sumA += e0 + e1;
                sumB += e2 + e3;
                __half* Hz = Chi + (size_t)blockIdx.z * sC;
                *(__half2*)&Hz[(size_t)row * N + col]       = __floats2half2_rn(e0, e1);
                *(__half2*)&Hz[(size_t)(row + 8) * N + col] = __floats2half2_rn(e2, e3);
            } else {  // OUTMODE 2
                if (rowsum) { v[0] *= inv0; v[1] *= inv0; v[2] *= inv1; v[3] *= inv1; }
                __half* Hz = Chi + (size_t)blockIdx.z * sC;
                *(__half2*)&Hz[(size_t)row * N + col]       = __floats2half2_rn(v[0], v[1]);
                *(__half2*)&Hz[(size_t)(row + 8) * N + col] = __floats2half2_rn(v[2], v[3]);
            }
        }
        if (OUTMODE == 3) {
            // reduce across the 4-lane quad sharing this row (lid&3 = 0..3)
            sumA += __shfl_xor_sync(0xffffffffu, sumA, 1);
            sumA += __shfl_xor_sync(0xffffffffu, sumA, 2);
            sumB += __shfl_xor_sync(0xffffffffu, sumB, 1);
            sumB += __shfl_xor_sync(0xffffffffu, sumB, 2);
            if ((lid & 3) == 0) {
                atomicAdd(&rowsum[(size_t)blockIdx.z * Mb + row], sumA);
                atomicAdd(&rowsum[(size_t)blockIdx.z * Mb + row + 8], sumB);
            }
        }
    }
}

// ---------------------------------------------------------------------------
// x -> fp16 (hi only)
// ---------------------------------------------------------------------------
__global__ __launch_bounds__(256)
void conv_f32_f16(const float4* __restrict__ in, __half* __restrict__ hi, size_t n4)
{
    size_t i = (size_t)blockIdx.x * 256 + threadIdx.x;
    if (i >= n4) return;
    float4 v = in[i];
    __half2 a = __floats2half2_rn(v.x, v.y);
    __half2 b = __floats2half2_rn(v.z, v.w);
    uint2 u; u.x = *(uint32_t*)&a; u.y = *(uint32_t*)&b;
    *(uint2*)(hi + i * 4) = u;
}

// ---------------------------------------------------------------------------
// Weight transposed split: fp32 [R,C] -> hi (optional lo) fp16 [C,R]
// ---------------------------------------------------------------------------
__global__ __launch_bounds__(256)
void tsplit_f32(const float* __restrict__ in, __half* __restrict__ hi,
                __half* __restrict__ lo, int R, int C)
{
    __shared__ float t[32][33];
    int c0 = blockIdx.x * 32, r0 = blockIdx.y * 32;
    int tx = threadIdx.x, ty = threadIdx.y;
#pragma unroll
    for (int i = 0; i < 32; i += 8)
        t[ty + i][tx] = in[(size_t)(r0 + ty + i) * C + c0 + tx];
    __syncthreads();
#pragma unroll
    for (int i = 0; i < 32; i += 8) {
        float v = t[tx][ty + i];
        __half h = __float2half_rn(v);
        size_t o = (size_t)(c0 + ty + i) * R + r0 + tx;
        hi[o] = h;
        if (lo) lo[o] = __float2half_rn(v - __half2float(h));
    }
}

// ---------------------------------------------------------------------------
// fp16 transpose: v slice of g_qkv [per batch 4096 x 512, ld 1536] -> [512, 4096]
// ---------------------------------------------------------------------------
__global__ __launch_bounds__(256)
void transpose_f16(const __half* __restrict__ in, __half* __restrict__ out,
                   int R, int C, int ldin, size_t sin, size_t sout)
{
    __shared__ __half t[32][33];
    in  += (size_t)blockIdx.z * sin;
    out += (size_t)blockIdx.z * sout;
    int c0 = blockIdx.x * 32, r0 = blockIdx.y * 32;
    int tx = threadIdx.x, ty = threadIdx.y;
#pragma unroll
    for (int i = 0; i < 32; i += 8)
        t[ty + i][tx] = in[(size_t)(r0 + ty + i) * ldin + c0 + tx];
    __syncthreads();
#pragma unroll
    for (int i = 0; i < 32; i += 8)
        out[(size_t)(c0 + ty + i) * R + r0 + tx] = t[tx][ty + i];
}

// ---------------------------------------------------------------------------
// bias concat + rowsum zero
// ---------------------------------------------------------------------------
__global__ void concat_bias(const float* bq, const float* bk, const float* bv,
                            float* dst)
{
    int i = blockIdx.x * 256 + threadIdx.x;
    if (i < 512)        dst[i] = bq[i];
    else if (i < 1024)  dst[i] = bk[i - 512];
    else if (i < 1536)  dst[i] = bv[i - 1024];
}

__global__ void zero_f32(float* p, int n)
{
    int i = blockIdx.x * 256 + threadIdx.x;
    if (i < n) p[i] = 0.f;
}

// ---------------------------------------------------------------------------
// kernel_launch
// ---------------------------------------------------------------------------
extern "C" void kernel_launch(void* const* d_in, const int* in_sizes, int n_in,
                              void* d_out, int out_size)
{
    (void)in_sizes; (void)n_in; (void)out_size;
    const float* x  = (const float*)d_in[0];
    const float* Wq = (const float*)d_in[1];
    const float* bq = (const float*)d_in[2];
    const float* Wk = (const float*)d_in[3];
    const float* bk = (const float*)d_in[4];
    const float* Wv = (const float*)d_in[5];
    const float* bv = (const float*)d_in[6];
    const float* Wo = (const float*)d_in[7];
    const float* bo = (const float*)d_in[8];
    float* out = (float*)d_out;

    __half *xhi, *qkv, *vthi, *atthi, *wthi, *wolo, *phi;
    float *bqkv, *rowsum;
    cudaGetSymbolAddress((void**)&xhi,    g_xhi);
    cudaGetSymbolAddress((void**)&qkv,    g_qkv);
    cudaGetSymbolAddress((void**)&vthi,   g_vthi);
    cudaGetSymbolAddress((void**)&atthi,  g_atthi);
    cudaGetSymbolAddress((void**)&wthi,   g_wthi);
    cudaGetSymbolAddress((void**)&wolo,   g_wolo);
    cudaGetSymbolAddress((void**)&bqkv,   g_bqkv);
    cudaGetSymbolAddress((void**)&phi,    g_phi);
    cudaGetSymbolAddress((void**)&rowsum, g_rowsum);

    const int SM2 = NSTAGES * 3 * TILE_B;   // 96 KB (2-term)
    const int SM1 = NSTAGES * 2 * TILE_B;   // 64 KB (1-term)
    cudaFuncSetAttribute(gemm_fp16<1,2>, cudaFuncAttributeMaxDynamicSharedMemorySize, SM1);
    cudaFuncSetAttribute(gemm_fp16<1,3>, cudaFuncAttributeMaxDynamicSharedMemorySize, SM1);
    cudaFuncSetAttribute(gemm_fp16<2,0>, cudaFuncAttributeMaxDynamicSharedMemorySize, SM2);

    const size_t WSLICE = (size_t)Dm * Pm;
    dim3 tblk(32, 8);

    // 1) weights -> W^T (hi for QKV; hi+lo for Wo)
    tsplit_f32<<<dim3(Pm/32, Dm/32, 1), tblk>>>(Wq, wthi + 0*WSLICE, nullptr, Dm, Pm);
    tsplit_f32<<<dim3(Pm/32, Dm/32, 1), tblk>>>(Wk, wthi + 1*WSLICE, nullptr, Dm, Pm);
    tsplit_f32<<<dim3(Pm/32, Dm/32, 1), tblk>>>(Wv, wthi + 2*WSLICE, nullptr, Dm, Pm);
    tsplit_f32<<<dim3(Dm/32, Pm/32, 1), tblk>>>(Wo, wthi + 3*WSLICE, wolo, Pm, Dm);
    concat_bias<<<6, 256>>>(bq, bk, bv, bqkv);
    zero_f32<<<Mrows / 256, 256>>>(rowsum, Mrows);

    // 2) x -> fp16 hi
    {
        size_t n4 = (size_t)Mrows * Dm / 4;
        conv_f32_f16<<<(unsigned)((n4 + 255) / 256), 256>>>((const float4*)x, xhi, n4);
    }

    // 3) fused QKV: [16384,1536] = x @ [Wq|Wk|Wv]^T + b  (1-term, fp16-hi out)
    {
        dim3 g(QKVN / 128, Mrows / 128, 1);   // (12,128,1)
        gemm_fp16<1,2><<<g, NTHR, SM1>>>(xhi, wthi, nullptr,
                                         bqkv, nullptr, nullptr, qkv,
                                         Dm, Dm, Dm, 1.0f, 0, 0, (size_t)Mrows * QKVN);
    }

    // 4) v transpose (fp16): per batch [4096,512] (ld 1536) -> [512,4096]
    transpose_f16<<<dim3(Pm/32, Sseq/32, Bsz), tblk>>>(
        qkv + 1024, vthi, Sseq, Pm, QKVN,
        (size_t)Sseq * QKVN, (size_t)Pm * Sseq);

    // 5) exp-scores = exp((q @ k^T)/8) fp16 + atomic rowsum (1-term)
    {
        dim3 g(Sseq / 128, Sseq / 128, Bsz);  // (32,32,4)
        gemm_fp16<1,3><<<g, NTHR, SM1>>>(qkv + 0, qkv + 512, nullptr,
                                         nullptr, rowsum, nullptr, phi,
                                         Pm, QKVN, QKVN, 0.125f,
                                         (size_t)Sseq * QKVN, (size_t)Sseq * QKVN,
                                         (size_t)Sseq * Sseq);
    }

    // 6) att = (exp-probs @ v) / rowsum   (1-term, fp16 hi out)
    {
        dim3 g(Pm / 128, Sseq / 128, Bsz);    // (4,32,4)
        gemm_fp16<1,2><<<g, NTHR, SM1>>>(phi, vthi, nullptr,
                                         nullptr, rowsum, nullptr, atthi,
                                         Sseq, Sseq, Sseq, 1.0f,
                                         (size_t)Sseq * Sseq, (size_t)Pm * Sseq,
                                         (size_t)Sseq * Pm);
    }

    // 7) out = att @ (Wo^T hi + Wo^T lo) + bo   (2-term, fp32)
    {
        dim3 g(Dm / 128, Mrows / 128, 1);     // (4,128,1)
        gemm_fp16<2,0><<<g, NTHR, SM2>>>(atthi, wthi + 3*WSLICE, wolo,
                                         bo, nullptr, out, nullptr,
                                         Pm, Pm, Pm, 1.0f, 0, 0, 0);
    }
}